// round 4
// baseline (speedup 1.0000x reference)
#include <cuda_runtime.h>
#include <cstdint>

// Problem constants
#define Bb 2
#define Nn 2048
#define Dd 1024
#define Hh 16
#define HD 64
#define Mm (Bb * Nn)          // 4096 tokens
#define QKVC 3072

// ---------------------------------------------------------------------------
// Scratch (device globals; no dynamic allocation allowed)
// ---------------------------------------------------------------------------
__device__ float g_q[Bb * Hh * Nn * HD];
__device__ float g_k[Bb * Hh * Nn * HD];
__device__ float g_v[Bb * Hh * Nn * HD];
__device__ float g_attn[Mm * Dd];

// ---------------------------------------------------------------------------
// Packed f32x2 helpers
// ---------------------------------------------------------------------------
__device__ __forceinline__ unsigned long long pk2(float lo, float hi) {
    unsigned long long r;
    asm("mov.b64 %0, {%1, %2};" : "=l"(r) : "f"(lo), "f"(hi));
    return r;
}
__device__ __forceinline__ void upk2(unsigned long long v, float& lo, float& hi) {
    asm("mov.b64 {%0, %1}, %2;" : "=f"(lo), "=f"(hi) : "l"(v));
}
__device__ __forceinline__ void fma2(unsigned long long& d, unsigned long long a,
                                     unsigned long long b) {
    asm("fma.rn.f32x2 %0, %1, %2, %0;" : "+l"(d) : "l"(a), "l"(b));
}
__device__ __forceinline__ void mul2(unsigned long long& d, unsigned long long b) {
    asm("mul.rn.f32x2 %0, %0, %1;" : "+l"(d) : "l"(b));
}

// ---------------------------------------------------------------------------
// GEMM core: C[128x128] tile, BK=8, 256 threads, 8x8 microtile (row pairs
// packed for f32x2), smem ping-pong double buffering (one barrier per k-tile).
// ---------------------------------------------------------------------------
struct GemmFrag {
    unsigned long long acc[4][8];
};

template <int LDB_N>
__device__ __forceinline__ void gemm_mainloop(
    const float* __restrict__ A, const float* __restrict__ Bw,
    int m0, int n0, int Kdim, GemmFrag& fr,
    float (*As)[8][132], float (*Bs)[8][128]) {
    const int tid  = threadIdx.x;
    const int tx   = tid & 15, ty = tid >> 4;
    const int arow = tid >> 1;
    const int akq  = (tid & 1) * 4;
    const int brow = tid >> 5;
    const int bcol = (tid & 31) * 4;

#pragma unroll
    for (int i = 0; i < 4; i++)
#pragma unroll
        for (int j = 0; j < 8; j++) fr.acc[i][j] = 0ull;

    const int KT = Kdim / 8;

    {   // Prologue: tile 0 into buffer 0
        float4 av = *(const float4*)(A  + (size_t)(m0 + arow) * Kdim + akq);
        float4 bv = *(const float4*)(Bw + (size_t)brow * LDB_N + n0 + bcol);
        As[0][akq + 0][arow] = av.x;
        As[0][akq + 1][arow] = av.y;
        As[0][akq + 2][arow] = av.z;
        As[0][akq + 3][arow] = av.w;
        *(float4*)&Bs[0][brow][bcol] = bv;
    }
    __syncthreads();

    for (int kt = 0; kt < KT; kt++) {
        const int cur = kt & 1;
        float4 av, bv;
        const bool has_next = (kt + 1 < KT);
        if (has_next) {
            int k0 = (kt + 1) * 8;
            av = *(const float4*)(A  + (size_t)(m0 + arow) * Kdim + k0 + akq);
            bv = *(const float4*)(Bw + (size_t)(k0 + brow) * LDB_N + n0 + bcol);
        }
#pragma unroll
        for (int kk = 0; kk < 8; kk++) {
            unsigned long long a2[4];
#pragma unroll
            for (int i2 = 0; i2 < 4; i2++)
                a2[i2] = *(const unsigned long long*)&As[cur][kk][ty * 8 + i2 * 2];
            float bq[8];
            *(float4*)&bq[0] = *(const float4*)&Bs[cur][kk][tx * 8];
            *(float4*)&bq[4] = *(const float4*)&Bs[cur][kk][tx * 8 + 4];
#pragma unroll
            for (int j = 0; j < 8; j++) {
                unsigned long long b2 = pk2(bq[j], bq[j]);
#pragma unroll
                for (int i2 = 0; i2 < 4; i2++) fma2(fr.acc[i2][j], a2[i2], b2);
            }
        }
        if (has_next) {
            const int nxt = cur ^ 1;
            As[nxt][akq + 0][arow] = av.x;
            As[nxt][akq + 1][arow] = av.y;
            As[nxt][akq + 2][arow] = av.z;
            As[nxt][akq + 3][arow] = av.w;
            *(float4*)&Bs[nxt][brow][bcol] = bv;
            __syncthreads();
        }
    }
}

// ---------------------------------------------------------------------------
// GEMM 1: qkv = x @ w_qkv + b_qkv, scattered into g_q / g_k / g_v
// ---------------------------------------------------------------------------
__device__ __forceinline__ void qkv_store(int m, int c, float v) {
    int part = c >> 10;        // 0=q, 1=k, 2=v
    int rem  = c & 1023;
    int h    = rem >> 6;
    int d    = rem & 63;
    int b    = m >> 11;
    int n    = m & 2047;
    float* dst = (part == 0) ? g_q : (part == 1) ? g_k : g_v;
    dst[(((size_t)b * Hh + h) * Nn + n) * HD + d] = v;
}

__global__ __launch_bounds__(256)
void qkv_gemm_kernel(const float* __restrict__ A, const float* __restrict__ Bw,
                     const float* __restrict__ bias) {
    __shared__ float As[2][8][132];
    __shared__ float Bs[2][8][128];
    const int tid = threadIdx.x;
    const int tx  = tid & 15, ty = tid >> 4;
    const int m0  = blockIdx.y * 128;
    const int n0  = blockIdx.x * 128;

    GemmFrag fr;
    gemm_mainloop<QKVC>(A, Bw, m0, n0, Dd, fr, As, Bs);

#pragma unroll
    for (int i2 = 0; i2 < 4; i2++) {
#pragma unroll
        for (int j = 0; j < 8; j++) {
            float lo, hi;
            upk2(fr.acc[i2][j], lo, hi);
            int c = n0 + tx * 8 + j;
            float bv = bias[c];
            int m = m0 + ty * 8 + i2 * 2;
            qkv_store(m,     c, lo + bv);
            qkv_store(m + 1, c, hi + bv);
        }
    }
}

// ---------------------------------------------------------------------------
// GEMM 2: out = g_attn @ w_proj + b_proj
// ---------------------------------------------------------------------------
__global__ __launch_bounds__(256)
void proj_gemm_kernel(const float* __restrict__ Bw, const float* __restrict__ bias,
                      float* __restrict__ out) {
    __shared__ float As[2][8][132];
    __shared__ float Bs[2][8][128];
    const int tid = threadIdx.x;
    const int tx  = tid & 15, ty = tid >> 4;
    const int m0  = blockIdx.y * 128;
    const int n0  = blockIdx.x * 128;

    GemmFrag fr;
    gemm_mainloop<Dd>(g_attn, Bw, m0, n0, Dd, fr, As, Bs);

#pragma unroll
    for (int i2 = 0; i2 < 4; i2++) {
#pragma unroll
        for (int j = 0; j < 8; j++) {
            float lo, hi;
            upk2(fr.acc[i2][j], lo, hi);
            int c = n0 + tx * 8 + j;
            float bv = bias[c];
            int m = m0 + ty * 8 + i2 * 2;
            out[(size_t)m * Dd + c]       = lo + bv;
            out[(size_t)(m + 1) * Dd + c] = hi + bv;
        }
    }
}

// ---------------------------------------------------------------------------
// Flash attention, fp32, f32x2-packed with dup-layout smem (no per-iteration
// pack MOVs in the hot loops).
//
// Layouts (all strides even -> 8B-aligned pair loads):
//   Qd [d][2q]   stride 130: Q value duplicated in both lanes (q = 0..63)
//   Kt [d][k]    stride 66 : K transposed, natural (pairs of k = LDS.64)
//   Pd [k][2q]   stride 130: P duplicated (written per tile; shares Kt region)
//   Vs [k][d]    stride 66 : V natural (pairs of d = LDS.64)
//
// 256 threads as 16x16 (tx,ty); thread owns q rows 4ty..+3, k cols 4tx..+3
// in S (accumulator packed over k pairs), and q rows 4ty..+3, d cols 4tx..+3
// in O (accumulator packed over d pairs).
// ---------------------------------------------------------------------------
#define TS 66
#define SD 130
#define ATTN_QD_OFF 0
#define ATTN_KP_OFF (64 * SD)
#define ATTN_VS_OFF (64 * SD + 64 * SD)
#define ATTN_BIAS_OFF (ATTN_VS_OFF + 64 * TS)
#define ATTN_SMEM_FLOATS (ATTN_BIAS_OFF + 64)
#define ATTN_SMEM_BYTES  (ATTN_SMEM_FLOATS * 4)

__global__ __launch_bounds__(256)
void attn_kernel(const float* __restrict__ attn_bias) {
    extern __shared__ float sm[];
    float* Qd     = sm + ATTN_QD_OFF;   // dup, stride SD
    float* KP     = sm + ATTN_KP_OFF;   // Kt (stride TS) then Pd (stride SD)
    float* Vs     = sm + ATTN_VS_OFF;   // stride TS
    float* bias_s = sm + ATTN_BIAS_OFF;

    const int tid = threadIdx.x;
    const int tx  = tid & 15, ty = tid >> 4;
    const int bh  = blockIdx.y;         // b*16 + h
    const int bb  = bh >> 4;
    const int q0  = blockIdx.x * 64;

    const float* Qg = g_q + ((size_t)bh * Nn + q0) * HD;
    const float* Kg = g_k + (size_t)bh * Nn * HD;
    const float* Vg = g_v + (size_t)bh * Nn * HD;
    const float* bg = attn_bias + (size_t)bb * Nn;

    // Load Q transposed + duplicated: Qd[d*SD + 2q] = Qd[.. + 2q+1] = Q[q][d]
#pragma unroll
    for (int i = 0; i < 4; i++) {
        int f  = i * 256 + tid;      // float4 index, 0..1023
        int q  = f >> 4;
        int d4 = (f & 15) << 2;
        float4 v = *(const float4*)(Qg + (size_t)q * HD + d4);
        *(unsigned long long*)&Qd[(d4 + 0) * SD + 2 * q] = pk2(v.x, v.x);
        *(unsigned long long*)&Qd[(d4 + 1) * SD + 2 * q] = pk2(v.y, v.y);
        *(unsigned long long*)&Qd[(d4 + 2) * SD + 2 * q] = pk2(v.z, v.z);
        *(unsigned long long*)&Qd[(d4 + 3) * SD + 2 * q] = pk2(v.w, v.w);
    }

    float m_i[4], l_i[4];
    unsigned long long o2[4][2];   // [q row i][d-col pair j2]; lo = col 4tx+2j2
#pragma unroll
    for (int i = 0; i < 4; i++) { m_i[i] = -1e30f; l_i[i] = 0.0f; }
#pragma unroll
    for (int i = 0; i < 4; i++)
#pragma unroll
        for (int j2 = 0; j2 < 2; j2++) o2[i][j2] = 0ull;

    for (int kt = 0; kt < Nn / 64; kt++) {
        const int k0 = kt * 64;
        __syncthreads();   // previous PV reads done
        // K tile, transposed natural: Kt[d*TS + k]
#pragma unroll
        for (int i = 0; i < 4; i++) {
            int f  = i * 256 + tid;
            int r  = f >> 4;
            int d4 = (f & 15) << 2;
            float4 v = *(const float4*)(Kg + (size_t)(k0 + r) * HD + d4);
            KP[(d4 + 0) * TS + r] = v.x;
            KP[(d4 + 1) * TS + r] = v.y;
            KP[(d4 + 2) * TS + r] = v.z;
            KP[(d4 + 3) * TS + r] = v.w;
        }
        // V tile, natural: Vs[k*TS + d]
#pragma unroll
        for (int i = 0; i < 4; i++) {
            int f  = i * 256 + tid;
            int r  = f >> 4;
            int d4 = (f & 15) << 2;
            float4 v = *(const float4*)(Vg + (size_t)(k0 + r) * HD + d4);
            Vs[r * TS + d4 + 0] = v.x;
            Vs[r * TS + d4 + 1] = v.y;
            Vs[r * TS + d4 + 2] = v.z;
            Vs[r * TS + d4 + 3] = v.w;
        }
        if (tid < 64) bias_s[tid] = bg[k0 + tid];
        __syncthreads();

        // S = Q K^T: accumulator packed over k pairs.
        // s2[i][j2]: lo = S[4ty+i][4tx+2j2], hi = S[4ty+i][4tx+2j2+1]
        unsigned long long s2[4][2];
#pragma unroll
        for (int i = 0; i < 4; i++)
#pragma unroll
            for (int j2 = 0; j2 < 2; j2++) s2[i][j2] = 0ull;

#pragma unroll 2
        for (int d = 0; d < 64; d++) {
            unsigned long long qd[4];
#pragma unroll
            for (int i = 0; i < 4; i++)
                qd[i] = *(const unsigned long long*)&Qd[d * SD + 2 * (ty * 4 + i)];
            unsigned long long kv2[2];
#pragma unroll
            for (int j2 = 0; j2 < 2; j2++)
                kv2[j2] = *(const unsigned long long*)&KP[d * TS + tx * 4 + 2 * j2];
#pragma unroll
            for (int i = 0; i < 4; i++)
#pragma unroll
                for (int j2 = 0; j2 < 2; j2++) fma2(s2[i][j2], qd[i], kv2[j2]);
        }
        // unpack, scale, bias
        float s[4][4];
#pragma unroll
        for (int i = 0; i < 4; i++)
#pragma unroll
            for (int j2 = 0; j2 < 2; j2++)
                upk2(s2[i][j2], s[i][2 * j2], s[i][2 * j2 + 1]);
        float bl[4];
#pragma unroll
        for (int j = 0; j < 4; j++) bl[j] = bias_s[tx * 4 + j];
#pragma unroll
        for (int i = 0; i < 4; i++)
#pragma unroll
            for (int j = 0; j < 4; j++) s[i][j] = s[i][j] * 0.125f + bl[j];

        // Online softmax per q row (16 lanes per row, shfl width 16)
        float corr[4];
#pragma unroll
        for (int i = 0; i < 4; i++) {
            float rm = fmaxf(fmaxf(s[i][0], s[i][1]), fmaxf(s[i][2], s[i][3]));
#pragma unroll
            for (int off = 8; off >= 1; off >>= 1)
                rm = fmaxf(rm, __shfl_xor_sync(0xffffffffu, rm, off, 16));
            float mn = fmaxf(m_i[i], rm);
            corr[i]  = __expf(m_i[i] - mn);
            m_i[i]   = mn;
            float rs = 0.0f;
#pragma unroll
            for (int j = 0; j < 4; j++) {
                s[i][j] = __expf(s[i][j] - mn);
                rs += s[i][j];
            }
#pragma unroll
            for (int off = 8; off >= 1; off >>= 1)
                rs += __shfl_xor_sync(0xffffffffu, rs, off, 16);
            l_i[i] = l_i[i] * corr[i] + rs;
        }
        // rescale O accumulators (per q row)
#pragma unroll
        for (int i = 0; i < 4; i++) {
            unsigned long long c2 = pk2(corr[i], corr[i]);
#pragma unroll
            for (int j2 = 0; j2 < 2; j2++) mul2(o2[i][j2], c2);
        }

        __syncthreads();   // all lanes done reading Kt from KP
        // write P duplicated: Pd[k*SD + 2q] (both lanes = P[k][q])
#pragma unroll
        for (int i = 0; i < 4; i++)
#pragma unroll
            for (int j = 0; j < 4; j++)
                *(unsigned long long*)&KP[(tx * 4 + j) * SD + 2 * (ty * 4 + i)] =
                    pk2(s[i][j], s[i][j]);
        __syncthreads();

        // O += P V: P dup loads (broadcast), V natural pairs.
#pragma unroll 2
        for (int k = 0; k < 64; k++) {
            unsigned long long pd[4];
#pragma unroll
            for (int i = 0; i < 4; i++)
                pd[i] = *(const unsigned long long*)&KP[k * SD + 2 * (ty * 4 + i)];
            unsigned long long vv2[2];
#pragma unroll
            for (int j2 = 0; j2 < 2; j2++)
                vv2[j2] = *(const unsigned long long*)&Vs[k * TS + tx * 4 + 2 * j2];
#pragma unroll
            for (int i = 0; i < 4; i++)
#pragma unroll
                for (int j2 = 0; j2 < 2; j2++) fma2(o2[i][j2], pd[i], vv2[j2]);
        }
    }

    // Write normalized output: g_attn[b*N + q][h*64 + d]
    const int h = bh & 15;
#pragma unroll
    for (int i = 0; i < 4; i++) {
        int q = q0 + ty * 4 + i;
        float inv = 1.0f / l_i[i];
#pragma unroll
        for (int j2 = 0; j2 < 2; j2++) {
            float lo, hi;
            upk2(o2[i][j2], lo, hi);
            size_t base = ((size_t)bb * Nn + q) * Dd + h * HD + tx * 4 + 2 * j2;
            g_attn[base]     = lo * inv;
            g_attn[base + 1] = hi * inv;
        }
    }
}

// ---------------------------------------------------------------------------
// Launch
// ---------------------------------------------------------------------------
extern "C" void kernel_launch(void* const* d_in, const int* in_sizes, int n_in,
                              void* d_out, int out_size) {
    const float* x         = (const float*)d_in[0];
    const float* attn_bias = (const float*)d_in[1];
    const float* w_qkv     = (const float*)d_in[2];
    const float* b_qkv     = (const float*)d_in[3];
    const float* w_proj    = (const float*)d_in[4];
    const float* b_proj    = (const float*)d_in[5];
    float* out             = (float*)d_out;

    cudaFuncSetAttribute(attn_kernel, cudaFuncAttributeMaxDynamicSharedMemorySize,
                         ATTN_SMEM_BYTES);

    qkv_gemm_kernel<<<dim3(QKVC / 128, Mm / 128), 256>>>(x, w_qkv, b_qkv);
    attn_kernel<<<dim3(Nn / 64, Bb * Hh), 256, ATTN_SMEM_BYTES>>>(attn_bias);
    proj_gemm_kernel<<<dim3(Dd / 128, Mm / 128), 256>>>(w_proj, b_proj, out);
}

// round 7
// speedup vs baseline: 2.0384x; 2.0384x over previous
#include <cuda_runtime.h>
#include <cuda_fp16.h>
#include <cstdint>

// Problem constants
#define Bb 2
#define Nn 2048
#define Dd 1024
#define Hh 16
#define HD 64
#define Mm (Bb * Nn)          // 4096 tokens
#define QKVC 3072

// ---------------------------------------------------------------------------
// Scratch (device globals; no dynamic allocation allowed)
// ---------------------------------------------------------------------------
__device__ float g_q[Bb * Hh * Nn * HD];
__device__ float g_k[Bb * Hh * Nn * HD];
__device__ float g_v[Bb * Hh * Nn * HD];
__device__ float g_attn[Mm * Dd];

// ---------------------------------------------------------------------------
// Packed f32x2 helpers (GEMM kernels)
// ---------------------------------------------------------------------------
__device__ __forceinline__ unsigned long long pk2(float lo, float hi) {
    unsigned long long r;
    asm("mov.b64 %0, {%1, %2};" : "=l"(r) : "f"(lo), "f"(hi));
    return r;
}
__device__ __forceinline__ void upk2(unsigned long long v, float& lo, float& hi) {
    asm("mov.b64 {%0, %1}, %2;" : "=f"(lo), "=f"(hi) : "l"(v));
}
__device__ __forceinline__ void fma2(unsigned long long& d, unsigned long long a,
                                     unsigned long long b) {
    asm("fma.rn.f32x2 %0, %1, %2, %0;" : "+l"(d) : "l"(a), "l"(b));
}

// ---------------------------------------------------------------------------
// mma.sync helpers (baseline PTX, works on compute_103)
// ---------------------------------------------------------------------------
__device__ __forceinline__ uint32_t f2tf32(float x) {
    uint32_t r;
    asm("cvt.rna.tf32.f32 %0, %1;" : "=r"(r) : "f"(x));
    return r;
}
__device__ __forceinline__ float ex2f(float x) {
    float r;
    asm("ex2.approx.f32 %0, %1;" : "=f"(r) : "f"(x));
    return r;
}
__device__ __forceinline__ void mma_tf32(float* d, uint32_t a0, uint32_t a1,
                                         uint32_t a2, uint32_t a3,
                                         uint32_t b0, uint32_t b1) {
    asm volatile(
        "mma.sync.aligned.m16n8k8.row.col.f32.tf32.tf32.f32 "
        "{%0,%1,%2,%3}, {%4,%5,%6,%7}, {%8,%9}, {%0,%1,%2,%3};"
        : "+f"(d[0]), "+f"(d[1]), "+f"(d[2]), "+f"(d[3])
        : "r"(a0), "r"(a1), "r"(a2), "r"(a3), "r"(b0), "r"(b1));
}
__device__ __forceinline__ void mma_f16(float* d, uint32_t a0, uint32_t a1,
                                        uint32_t a2, uint32_t a3,
                                        uint32_t b0, uint32_t b1) {
    asm volatile(
        "mma.sync.aligned.m16n8k16.row.col.f32.f16.f16.f32 "
        "{%0,%1,%2,%3}, {%4,%5,%6,%7}, {%8,%9}, {%0,%1,%2,%3};"
        : "+f"(d[0]), "+f"(d[1]), "+f"(d[2]), "+f"(d[3])
        : "r"(a0), "r"(a1), "r"(a2), "r"(a3), "r"(b0), "r"(b1));
}
__device__ __forceinline__ uint32_t h2u(__half2 h) {
    uint32_t r;
    asm("mov.b32 %0, %1;" : "=r"(r) : "r"(*(uint32_t*)&h));
    return r;
}

// ---------------------------------------------------------------------------
// SIMT GEMM core (benched @ round 4): C[128x128], BK=8, 256 thr, f32x2,
// ping-pong double buffering.
// ---------------------------------------------------------------------------
struct GemmFrag {
    unsigned long long acc[4][8];
};

template <int LDB_N>
__device__ __forceinline__ void gemm_mainloop(
    const float* __restrict__ A, const float* __restrict__ Bw,
    int m0, int n0, int Kdim, GemmFrag& fr,
    float (*As)[8][132], float (*Bs)[8][128]) {
    const int tid  = threadIdx.x;
    const int tx   = tid & 15, ty = tid >> 4;
    const int arow = tid >> 1;
    const int akq  = (tid & 1) * 4;
    const int brow = tid >> 5;
    const int bcol = (tid & 31) * 4;

#pragma unroll
    for (int i = 0; i < 4; i++)
#pragma unroll
        for (int j = 0; j < 8; j++) fr.acc[i][j] = 0ull;

    const int KT = Kdim / 8;
    {
        float4 av = *(const float4*)(A  + (size_t)(m0 + arow) * Kdim + akq);
        float4 bv = *(const float4*)(Bw + (size_t)brow * LDB_N + n0 + bcol);
        As[0][akq + 0][arow] = av.x;
        As[0][akq + 1][arow] = av.y;
        As[0][akq + 2][arow] = av.z;
        As[0][akq + 3][arow] = av.w;
        *(float4*)&Bs[0][brow][bcol] = bv;
    }
    __syncthreads();

    for (int kt = 0; kt < KT; kt++) {
        const int cur = kt & 1;
        float4 av, bv;
        const bool has_next = (kt + 1 < KT);
        if (has_next) {
            int k0 = (kt + 1) * 8;
            av = *(const float4*)(A  + (size_t)(m0 + arow) * Kdim + k0 + akq);
            bv = *(const float4*)(Bw + (size_t)(k0 + brow) * LDB_N + n0 + bcol);
        }
#pragma unroll
        for (int kk = 0; kk < 8; kk++) {
            unsigned long long a2[4];
#pragma unroll
            for (int i2 = 0; i2 < 4; i2++)
                a2[i2] = *(const unsigned long long*)&As[cur][kk][ty * 8 + i2 * 2];
            float bq[8];
            *(float4*)&bq[0] = *(const float4*)&Bs[cur][kk][tx * 8];
            *(float4*)&bq[4] = *(const float4*)&Bs[cur][kk][tx * 8 + 4];
#pragma unroll
            for (int j = 0; j < 8; j++) {
                unsigned long long b2 = pk2(bq[j], bq[j]);
#pragma unroll
                for (int i2 = 0; i2 < 4; i2++) fma2(fr.acc[i2][j], a2[i2], b2);
            }
        }
        if (has_next) {
            const int nxt = cur ^ 1;
            As[nxt][akq + 0][arow] = av.x;
            As[nxt][akq + 1][arow] = av.y;
            As[nxt][akq + 2][arow] = av.z;
            As[nxt][akq + 3][arow] = av.w;
            *(float4*)&Bs[nxt][brow][bcol] = bv;
            __syncthreads();
        }
    }
}

__device__ __forceinline__ void qkv_store(int m, int c, float v) {
    int part = c >> 10;        // 0=q, 1=k, 2=v
    int rem  = c & 1023;
    int h    = rem >> 6;
    int d    = rem & 63;
    int b    = m >> 11;
    int n    = m & 2047;
    float* dst = (part == 0) ? g_q : (part == 1) ? g_k : g_v;
    dst[(((size_t)b * Hh + h) * Nn + n) * HD + d] = v;
}

__global__ __launch_bounds__(256)
void qkv_gemm_kernel(const float* __restrict__ A, const float* __restrict__ Bw,
                     const float* __restrict__ bias) {
    __shared__ float As[2][8][132];
    __shared__ float Bs[2][8][128];
    const int tid = threadIdx.x;
    const int tx  = tid & 15, ty = tid >> 4;
    const int m0  = blockIdx.y * 128;
    const int n0  = blockIdx.x * 128;

    GemmFrag fr;
    gemm_mainloop<QKVC>(A, Bw, m0, n0, Dd, fr, As, Bs);

#pragma unroll
    for (int i2 = 0; i2 < 4; i2++) {
#pragma unroll
        for (int j = 0; j < 8; j++) {
            float lo, hi;
            upk2(fr.acc[i2][j], lo, hi);
            int c = n0 + tx * 8 + j;
            float bv = bias[c];
            int m = m0 + ty * 8 + i2 * 2;
            qkv_store(m,     c, lo + bv);
            qkv_store(m + 1, c, hi + bv);
        }
    }
}

__global__ __launch_bounds__(256)
void proj_gemm_kernel(const float* __restrict__ Bw, const float* __restrict__ bias,
                      float* __restrict__ out) {
    __shared__ float As[2][8][132];
    __shared__ float Bs[2][8][128];
    const int tid = threadIdx.x;
    const int tx  = tid & 15, ty = tid >> 4;
    const int m0  = blockIdx.y * 128;
    const int n0  = blockIdx.x * 128;

    GemmFrag fr;
    gemm_mainloop<Dd>(g_attn, Bw, m0, n0, Dd, fr, As, Bs);

#pragma unroll
    for (int i2 = 0; i2 < 4; i2++) {
#pragma unroll
        for (int j = 0; j < 8; j++) {
            float lo, hi;
            upk2(fr.acc[i2][j], lo, hi);
            int c = n0 + tx * 8 + j;
            float bv = bias[c];
            int m = m0 + ty * 8 + i2 * 2;
            out[(size_t)m * Dd + c]       = lo + bv;
            out[(size_t)(m + 1) * Dd + c] = hi + bv;
        }
    }
}

// ---------------------------------------------------------------------------
// Flash attention on mma.sync.
//   S = Q K^T  via m16n8k8 tf32 (A=Q, B=K; both from interleaved-pair smem)
//   P V        via m16n8k16 f16 (A=P direct from S fragments, B=V^T fp16)
// CTA: 256 thr / 8 warps, Q-tile 128 rows (16 rows per warp), K-tile 64.
// Softmax in log2 domain (scores and bias pre-scaled by log2(e)).
//
// smem (bytes):
//   Qp  u64[128*36]  @0      : (tf32 d, tf32 d+4) pairs, row stride 36
//   Kp  u64[64*36]   @36864
//   Vt  half[64*68]  @55296  : V transposed [d][key], row stride 68
//   bias float[64]   @64000  : pre-scaled by log2(e)
// ---------------------------------------------------------------------------
#define SQP 36
#define SKP 36
#define VTS 68
#define ATTN_SMEM_BYTES (64000 + 256)
#define LOG2E 1.4426950408889634f

__global__ __launch_bounds__(256)
void attn_mma_kernel(const float* __restrict__ attn_bias) {
    extern __shared__ char smc[];
    unsigned long long* Qp = (unsigned long long*)smc;
    unsigned long long* Kp = (unsigned long long*)(smc + 36864);
    __half* Vt             = (__half*)(smc + 55296);
    float* bias_s          = (float*)(smc + 64000);

    const int tid  = threadIdx.x;
    const int lane = tid & 31;
    const int w    = tid >> 5;
    const int lq   = lane >> 2;     // 0..7
    const int lm   = lane & 3;      // 0..3
    const int bh   = blockIdx.y;    // b*16 + h
    const int bb   = bh >> 4;
    const int h    = bh & 15;
    const int q0   = blockIdx.x * 128;

    const float* Qg = g_q + ((size_t)bh * Nn + q0) * HD;
    const float* Kg = g_k + (size_t)bh * Nn * HD;
    const float* Vg = g_v + (size_t)bh * Nn * HD;
    const float* bg = attn_bias + (size_t)bb * Nn;

    // Load Q into interleaved tf32 pair layout: 128 rows x 8 chunks, 4 tasks/thr
#pragma unroll
    for (int t = 0; t < 4; t++) {
        int task = tid + t * 256;
        int row  = task >> 3;
        int ch   = task & 7;
        const float* src = Qg + (size_t)row * HD + ch * 8;
        float4 v0 = *(const float4*)src;
        float4 v1 = *(const float4*)(src + 4);
        unsigned long long* dst = Qp + row * SQP + ch * 4;
        dst[0] = (unsigned long long)f2tf32(v0.x) | ((unsigned long long)f2tf32(v1.x) << 32);
        dst[1] = (unsigned long long)f2tf32(v0.y) | ((unsigned long long)f2tf32(v1.y) << 32);
        dst[2] = (unsigned long long)f2tf32(v0.z) | ((unsigned long long)f2tf32(v1.z) << 32);
        dst[3] = (unsigned long long)f2tf32(v0.w) | ((unsigned long long)f2tf32(v1.w) << 32);
    }

    float m0r = -1e30f, m1r = -1e30f, l0 = 0.0f, l1 = 0.0f;
    float o[8][4];
#pragma unroll
    for (int nd = 0; nd < 8; nd++)
#pragma unroll
        for (int j = 0; j < 4; j++) o[nd][j] = 0.0f;

    const unsigned long long* Ar0 = Qp + (w * 16 + lq) * SQP;
    const unsigned long long* Ar1 = Ar0 + 8 * SQP;

    for (int kt = 0; kt < Nn / 64; kt++) {
        const int k0 = kt * 64;
        __syncthreads();
        // K tile: 64 keys x 8 chunks, 2 tasks/thr
#pragma unroll
        for (int t = 0; t < 2; t++) {
            int task = tid + t * 256;
            int key  = task >> 3;
            int ch   = task & 7;
            const float* src = Kg + (size_t)(k0 + key) * HD + ch * 8;
            float4 v0 = *(const float4*)src;
            float4 v1 = *(const float4*)(src + 4);
            unsigned long long* dst = Kp + key * SKP + ch * 4;
            dst[0] = (unsigned long long)f2tf32(v0.x) | ((unsigned long long)f2tf32(v1.x) << 32);
            dst[1] = (unsigned long long)f2tf32(v0.y) | ((unsigned long long)f2tf32(v1.y) << 32);
            dst[2] = (unsigned long long)f2tf32(v0.z) | ((unsigned long long)f2tf32(v1.z) << 32);
            dst[3] = (unsigned long long)f2tf32(v0.w) | ((unsigned long long)f2tf32(v1.w) << 32);
        }
        // V tile transposed fp16: 32 key-pairs x 16 d4-groups, 2 tasks/thr
#pragma unroll
        for (int t = 0; t < 2; t++) {
            int task = tid + t * 256;
            int kp   = task >> 4;
            int c4   = task & 15;
            const float* s0 = Vg + (size_t)(k0 + 2 * kp) * HD + c4 * 4;
            float4 a = *(const float4*)s0;
            float4 b = *(const float4*)(s0 + HD);
            *(__half2*)&Vt[(c4 * 4 + 0) * VTS + 2 * kp] = __floats2half2_rn(a.x, b.x);
            *(__half2*)&Vt[(c4 * 4 + 1) * VTS + 2 * kp] = __floats2half2_rn(a.y, b.y);
            *(__half2*)&Vt[(c4 * 4 + 2) * VTS + 2 * kp] = __floats2half2_rn(a.z, b.z);
            *(__half2*)&Vt[(c4 * 4 + 3) * VTS + 2 * kp] = __floats2half2_rn(a.w, b.w);
        }
        if (tid < 64) bias_s[tid] = bg[k0 + tid] * LOG2E;
        __syncthreads();

        // ---- S = Q K^T (tf32) ----
        float s[8][4];
#pragma unroll
        for (int nb = 0; nb < 8; nb++)
#pragma unroll
            for (int j = 0; j < 4; j++) s[nb][j] = 0.0f;

#pragma unroll
        for (int kk = 0; kk < 8; kk++) {
            uint2 a02 = *(const uint2*)&Ar0[kk * 4 + lm];
            uint2 a13 = *(const uint2*)&Ar1[kk * 4 + lm];
#pragma unroll
            for (int nb = 0; nb < 8; nb++) {
                uint2 b01 = *(const uint2*)&Kp[(nb * 8 + lq) * SKP + kk * 4 + lm];
                mma_tf32(s[nb], a02.x, a13.x, a02.y, a13.y, b01.x, b01.y);
            }
        }

        // scale (0.125*log2e) + bias (already *log2e)
        const float SC = 0.125f * LOG2E;
#pragma unroll
        for (int nb = 0; nb < 8; nb++) {
            float2 bv = *(const float2*)&bias_s[nb * 8 + 2 * lm];
            s[nb][0] = s[nb][0] * SC + bv.x;
            s[nb][1] = s[nb][1] * SC + bv.y;
            s[nb][2] = s[nb][2] * SC + bv.x;
            s[nb][3] = s[nb][3] * SC + bv.y;
        }

        // online softmax (log2 domain); rows r0=lane/4, r1=r0+8
        float rm0 = s[0][0], rm1 = s[0][2];
#pragma unroll
        for (int nb = 0; nb < 8; nb++) {
            rm0 = fmaxf(rm0, fmaxf(s[nb][0], s[nb][1]));
            rm1 = fmaxf(rm1, fmaxf(s[nb][2], s[nb][3]));
        }
        rm0 = fmaxf(rm0, __shfl_xor_sync(0xffffffffu, rm0, 1));
        rm0 = fmaxf(rm0, __shfl_xor_sync(0xffffffffu, rm0, 2));
        rm1 = fmaxf(rm1, __shfl_xor_sync(0xffffffffu, rm1, 1));
        rm1 = fmaxf(rm1, __shfl_xor_sync(0xffffffffu, rm1, 2));
        float mn0 = fmaxf(m0r, rm0), mn1 = fmaxf(m1r, rm1);
        float c0 = ex2f(m0r - mn0), c1 = ex2f(m1r - mn1);
        m0r = mn0; m1r = mn1;
        float rs0 = 0.0f, rs1 = 0.0f;
#pragma unroll
        for (int nb = 0; nb < 8; nb++) {
            s[nb][0] = ex2f(s[nb][0] - mn0);
            s[nb][1] = ex2f(s[nb][1] - mn0);
            s[nb][2] = ex2f(s[nb][2] - mn1);
            s[nb][3] = ex2f(s[nb][3] - mn1);
            rs0 += s[nb][0] + s[nb][1];
            rs1 += s[nb][2] + s[nb][3];
        }
        rs0 += __shfl_xor_sync(0xffffffffu, rs0, 1);
        rs0 += __shfl_xor_sync(0xffffffffu, rs0, 2);
        rs1 += __shfl_xor_sync(0xffffffffu, rs1, 1);
        rs1 += __shfl_xor_sync(0xffffffffu, rs1, 2);
        l0 = l0 * c0 + rs0;
        l1 = l1 * c1 + rs1;
#pragma unroll
        for (int nd = 0; nd < 8; nd++) {
            o[nd][0] *= c0; o[nd][1] *= c0;
            o[nd][2] *= c1; o[nd][3] *= c1;
        }

        // ---- O += P V (fp16); P fragments come straight from s ----
#pragma unroll
        for (int kc = 0; kc < 4; kc++) {
            uint32_t a0 = h2u(__floats2half2_rn(s[2 * kc][0],     s[2 * kc][1]));
            uint32_t a1 = h2u(__floats2half2_rn(s[2 * kc][2],     s[2 * kc][3]));
            uint32_t a2 = h2u(__floats2half2_rn(s[2 * kc + 1][0], s[2 * kc + 1][1]));
            uint32_t a3 = h2u(__floats2half2_rn(s[2 * kc + 1][2], s[2 * kc + 1][3]));
#pragma unroll
            for (int nd = 0; nd < 8; nd++) {
                const __half* vb = &Vt[(nd * 8 + lq) * VTS + kc * 16 + 2 * lm];
                uint32_t b0 = *(const uint32_t*)vb;
                uint32_t b1 = *(const uint32_t*)(vb + 8);
                mma_f16(o[nd], a0, a1, a2, a3, b0, b1);
            }
        }
    }

    // Epilogue: normalize and write g_attn[b*N + q][h*64 + d]
    float inv0 = 1.0f / l0, inv1 = 1.0f / l1;
    int qr0 = q0 + w * 16 + lq;
    int qr1 = qr0 + 8;
#pragma unroll
    for (int nd = 0; nd < 8; nd++) {
        int col = h * HD + nd * 8 + 2 * lm;
        float2 v0 = make_float2(o[nd][0] * inv0, o[nd][1] * inv0);
        float2 v1 = make_float2(o[nd][2] * inv1, o[nd][3] * inv1);
        *(float2*)&g_attn[((size_t)bb * Nn + qr0) * Dd + col] = v0;
        *(float2*)&g_attn[((size_t)bb * Nn + qr1) * Dd + col] = v1;
    }
}

// ---------------------------------------------------------------------------
// Launch
// ---------------------------------------------------------------------------
extern "C" void kernel_launch(void* const* d_in, const int* in_sizes, int n_in,
                              void* d_out, int out_size) {
    const float* x         = (const float*)d_in[0];
    const float* attn_bias = (const float*)d_in[1];
    const float* w_qkv     = (const float*)d_in[2];
    const float* b_qkv     = (const float*)d_in[3];
    const float* w_proj    = (const float*)d_in[4];
    const float* b_proj    = (const float*)d_in[5];
    float* out             = (float*)d_out;

    cudaFuncSetAttribute(attn_mma_kernel, cudaFuncAttributeMaxDynamicSharedMemorySize,
                         ATTN_SMEM_BYTES);

    qkv_gemm_kernel<<<dim3(QKVC / 128, Mm / 128), 256>>>(x, w_qkv, b_qkv);
    attn_mma_kernel<<<dim3(Nn / 128, Bb * Hh), 256, ATTN_SMEM_BYTES>>>(attn_bias);
    proj_gemm_kernel<<<dim3(Dd / 128, Mm / 128), 256>>>(w_proj, b_proj, out);
}

// round 8
// speedup vs baseline: 2.5210x; 1.2368x over previous
#include <cuda_runtime.h>
#include <cuda_fp16.h>
#include <cstdint>

// Problem constants
#define Bb 2
#define Nn 2048
#define Dd 1024
#define Hh 16
#define HD 64
#define Mm (Bb * Nn)          // 4096 tokens
#define QKVC 3072

// ---------------------------------------------------------------------------
// Scratch (device globals; no dynamic allocation allowed)
// ---------------------------------------------------------------------------
__device__ float g_q[Bb * Hh * Nn * HD];
__device__ float g_k[Bb * Hh * Nn * HD];
__device__ float g_v[Bb * Hh * Nn * HD];
__device__ float g_attn[Mm * Dd];

// ---------------------------------------------------------------------------
// Common helpers
// ---------------------------------------------------------------------------
__device__ __forceinline__ uint32_t smem_u32(const void* p) {
    uint32_t a;
    asm("{ .reg .u64 t; cvta.to.shared.u64 t, %1; cvt.u32.u64 %0, t; }"
        : "=r"(a) : "l"(p));
    return a;
}
__device__ __forceinline__ uint32_t f2tf32(float x) {
    uint32_t r;
    asm("cvt.rna.tf32.f32 %0, %1;" : "=r"(r) : "f"(x));
    return r;
}
__device__ __forceinline__ float ex2f(float x) {
    float r;
    asm("ex2.approx.f32 %0, %1;" : "=f"(r) : "f"(x));
    return r;
}
__device__ __forceinline__ void mma_tf32(float* d, uint32_t a0, uint32_t a1,
                                         uint32_t a2, uint32_t a3,
                                         uint32_t b0, uint32_t b1) {
    asm volatile(
        "mma.sync.aligned.m16n8k8.row.col.f32.tf32.tf32.f32 "
        "{%0,%1,%2,%3}, {%4,%5,%6,%7}, {%8,%9}, {%0,%1,%2,%3};"
        : "+f"(d[0]), "+f"(d[1]), "+f"(d[2]), "+f"(d[3])
        : "r"(a0), "r"(a1), "r"(a2), "r"(a3), "r"(b0), "r"(b1));
}
__device__ __forceinline__ void mma_f16(float* d, uint32_t a0, uint32_t a1,
                                        uint32_t a2, uint32_t a3,
                                        uint32_t b0, uint32_t b1) {
    asm volatile(
        "mma.sync.aligned.m16n8k16.row.col.f32.f16.f16.f32 "
        "{%0,%1,%2,%3}, {%4,%5,%6,%7}, {%8,%9}, {%0,%1,%2,%3};"
        : "+f"(d[0]), "+f"(d[1]), "+f"(d[2]), "+f"(d[3])
        : "r"(a0), "r"(a1), "r"(a2), "r"(a3), "r"(b0), "r"(b1));
}
__device__ __forceinline__ uint32_t h2u(__half2 h) {
    return *(uint32_t*)&h;
}
#define LDSM4(r0, r1, r2, r3, addr) \
    asm volatile("ldmatrix.sync.aligned.m8n8.x4.shared.b16 {%0,%1,%2,%3}, [%4];" \
                 : "=r"(r0), "=r"(r1), "=r"(r2), "=r"(r3) : "r"(addr))
#define LDSM4T(r0, r1, r2, r3, addr) \
    asm volatile("ldmatrix.sync.aligned.m8n8.x4.trans.shared.b16 {%0,%1,%2,%3}, [%4];" \
                 : "=r"(r0), "=r"(r1), "=r"(r2), "=r"(r3) : "r"(addr))
#define STS64U(addr, x, y) \
    asm volatile("st.shared.v2.b32 [%0], {%1, %2};" :: "r"(addr), "r"(x), "r"(y) : "memory")

// Split fp32 pair into hi/lo fp16 pairs (3xFP16 emulation)
__device__ __forceinline__ void split2(float a, float b, uint32_t& h, uint32_t& l) {
    __half ha = __float2half_rn(a), hb = __float2half_rn(b);
    __half la = __float2half_rn(a - __half2float(ha));
    __half lb = __float2half_rn(b - __half2float(hb));
    h = h2u(__halves2half2(ha, hb));
    l = h2u(__halves2half2(la, lb));
}

// ---------------------------------------------------------------------------
// 3xFP16 mma.sync GEMM. CTA 128x128, 256 thr / 8 warps (warp tile 32x64),
// BK=32, smem ping-pong. A[M,K], B[K,N] row-major fp32 gmem; each value is
// split x = hi + lo (fp16); accumulate Ah*Bh + Ah*Bl + Al*Bh in fp32.
// smem: A planes [128][40] halfs (80B stride, ldmatrix conflict-free),
//       B planes [32][136] halfs (272B stride, ldmatrix.trans conflict-free).
// MODE 0: epilogue scatters qkv to g_q/g_k/g_v. MODE 1: proj -> out.
// ---------------------------------------------------------------------------
#define A_PLANE 10240           // 128*80 bytes
#define B_PLANE 8704            // 32*272 bytes
#define GEMM_SMEM_BYTES (4 * A_PLANE + 4 * B_PLANE)   // 75776

__device__ __forceinline__ void qkv_store2(int m, int c, float v0, float v1) {
    int part = c >> 10;        // 0=q, 1=k, 2=v
    int rem  = c & 1023;
    int h    = rem >> 6;
    int d    = rem & 63;
    int b    = m >> 11;
    int n    = m & 2047;
    float* dst = (part == 0) ? g_q : (part == 1) ? g_k : g_v;
    *(float2*)&dst[(((size_t)b * Hh + h) * Nn + n) * HD + d] = make_float2(v0, v1);
}

template <int NDIM, int MODE>
__global__ __launch_bounds__(256, 1)
void gemm_mma_kernel(const float* __restrict__ Ain,
                     const float* __restrict__ Bw,
                     const float* __restrict__ bias,
                     float* __restrict__ out) {
    extern __shared__ char smg[];
    const float* A = (MODE == 0) ? Ain : g_attn;

    const int tid  = threadIdx.x;
    const int lane = tid & 31;
    const int w    = tid >> 5;
    const int wm   = (w & 3) * 32;
    const int wn   = (w >> 2) * 64;
    const int m0   = blockIdx.y * 128;
    const int n0   = blockIdx.x * 128;

    const uint32_t sb  = smem_u32(smg);
    // layout: Ah[2], Al[2], Bh[2], Bl[2]
    const uint32_t sAh0 = sb;
    const uint32_t sAl0 = sb + 2 * A_PLANE;
    const uint32_t sBh0 = sb + 4 * A_PLANE;
    const uint32_t sBl0 = sb + 4 * A_PLANE + 2 * B_PLANE;

    float acc[2][8][4];
#pragma unroll
    for (int t = 0; t < 2; t++)
#pragma unroll
        for (int j = 0; j < 8; j++)
#pragma unroll
            for (int e = 0; e < 4; e++) acc[t][j][e] = 0.0f;

    // per-thread load/store coords
    const int arow[4] = { (tid + 0) >> 3, (tid + 256) >> 3,
                          (tid + 512) >> 3, (tid + 768) >> 3 };
    const int ac4  = tid & 7;
    const int bkk[4] = { (tid + 0) >> 5, (tid + 256) >> 5,
                         (tid + 512) >> 5, (tid + 768) >> 5 };
    const int bn4  = tid & 31;

    float4 av[4], bv[4];
    // prologue: chunk 0
#pragma unroll
    for (int i = 0; i < 4; i++) {
        av[i] = *(const float4*)(A  + (size_t)(m0 + arow[i]) * Dd + ac4 * 4);
        bv[i] = *(const float4*)(Bw + (size_t)bkk[i] * NDIM + n0 + bn4 * 4);
    }
#pragma unroll
    for (int i = 0; i < 4; i++) {
        uint32_t h01, l01, h23, l23;
        split2(av[i].x, av[i].y, h01, l01);
        split2(av[i].z, av[i].w, h23, l23);
        uint32_t aoff = (uint32_t)(arow[i] * 80 + ac4 * 8);
        STS64U(sAh0 + aoff, h01, h23);
        STS64U(sAl0 + aoff, l01, l23);
        split2(bv[i].x, bv[i].y, h01, l01);
        split2(bv[i].z, bv[i].w, h23, l23);
        uint32_t boff = (uint32_t)(bkk[i] * 272 + bn4 * 8);
        STS64U(sBh0 + boff, h01, h23);
        STS64U(sBl0 + boff, l01, l23);
    }
    __syncthreads();

    const uint32_t lA = (uint32_t)((lane & 15) * 80 + (lane >> 4) * 16);
    const uint32_t lB = (uint32_t)((lane & 15) * 272 + (lane >> 4) * 16);

    const int NCHUNK = Dd / 32;
    for (int c = 0; c < NCHUNK; c++) {
        const int cur = c & 1;
        const bool has_next = (c + 1 < NCHUNK);
        if (has_next) {
            int k0 = (c + 1) * 32;
#pragma unroll
            for (int i = 0; i < 4; i++) {
                av[i] = *(const float4*)(A  + (size_t)(m0 + arow[i]) * Dd + k0 + ac4 * 4);
                bv[i] = *(const float4*)(Bw + (size_t)(k0 + bkk[i]) * NDIM + n0 + bn4 * 4);
            }
        }
        const uint32_t cAh = sAh0 + cur * A_PLANE;
        const uint32_t cAl = sAl0 + cur * A_PLANE;
        const uint32_t cBh = sBh0 + cur * B_PLANE;
        const uint32_t cBl = sBl0 + cur * B_PLANE;

#pragma unroll
        for (int g = 0; g < 2; g++) {
            uint32_t ah[2][4], al[2][4];
#pragma unroll
            for (int t = 0; t < 2; t++) {
                uint32_t ab = (uint32_t)((wm + t * 16) * 80 + g * 32) + lA;
                LDSM4(ah[t][0], ah[t][1], ah[t][2], ah[t][3], cAh + ab);
                LDSM4(al[t][0], al[t][1], al[t][2], al[t][3], cAl + ab);
            }
#pragma unroll
            for (int j = 0; j < 4; j++) {
                uint32_t bb = (uint32_t)(g * 16 * 272 + (wn + j * 16) * 2) + lB;
                uint32_t bh[4], bl[4];
                LDSM4T(bh[0], bh[1], bh[2], bh[3], cBh + bb);
                LDSM4T(bl[0], bl[1], bl[2], bl[3], cBl + bb);
                // pass hi*hi
#pragma unroll
                for (int t = 0; t < 2; t++) {
                    mma_f16(acc[t][2 * j],     ah[t][0], ah[t][1], ah[t][2], ah[t][3], bh[0], bh[1]);
                    mma_f16(acc[t][2 * j + 1], ah[t][0], ah[t][1], ah[t][2], ah[t][3], bh[2], bh[3]);
                }
                // pass hi*lo
#pragma unroll
                for (int t = 0; t < 2; t++) {
                    mma_f16(acc[t][2 * j],     ah[t][0], ah[t][1], ah[t][2], ah[t][3], bl[0], bl[1]);
                    mma_f16(acc[t][2 * j + 1], ah[t][0], ah[t][1], ah[t][2], ah[t][3], bl[2], bl[3]);
                }
                // pass lo*hi
#pragma unroll
                for (int t = 0; t < 2; t++) {
                    mma_f16(acc[t][2 * j],     al[t][0], al[t][1], al[t][2], al[t][3], bh[0], bh[1]);
                    mma_f16(acc[t][2 * j + 1], al[t][0], al[t][1], al[t][2], al[t][3], bh[2], bh[3]);
                }
            }
        }

        if (has_next) {
            const int nxt = cur ^ 1;
            const uint32_t nAh = sAh0 + nxt * A_PLANE;
            const uint32_t nAl = sAl0 + nxt * A_PLANE;
            const uint32_t nBh = sBh0 + nxt * B_PLANE;
            const uint32_t nBl = sBl0 + nxt * B_PLANE;
#pragma unroll
            for (int i = 0; i < 4; i++) {
                uint32_t h01, l01, h23, l23;
                split2(av[i].x, av[i].y, h01, l01);
                split2(av[i].z, av[i].w, h23, l23);
                uint32_t aoff = (uint32_t)(arow[i] * 80 + ac4 * 8);
                STS64U(nAh + aoff, h01, h23);
                STS64U(nAl + aoff, l01, l23);
                split2(bv[i].x, bv[i].y, h01, l01);
                split2(bv[i].z, bv[i].w, h23, l23);
                uint32_t boff = (uint32_t)(bkk[i] * 272 + bn4 * 8);
                STS64U(nBh + boff, h01, h23);
                STS64U(nBl + boff, l01, l23);
            }
            __syncthreads();
        }
    }

    // Epilogue: D frag rows wm+t*16+(lane>>2)(+8), cols wn+jj*8+2*(lane&3)(+1)
#pragma unroll
    for (int t = 0; t < 2; t++) {
        int r0 = m0 + wm + t * 16 + (lane >> 2);
#pragma unroll
        for (int jj = 0; jj < 8; jj++) {
            int cc = n0 + wn + jj * 8 + 2 * (lane & 3);
            float b0 = bias[cc], b1 = bias[cc + 1];
            float v00 = acc[t][jj][0] + b0, v01 = acc[t][jj][1] + b1;
            float v10 = acc[t][jj][2] + b0, v11 = acc[t][jj][3] + b1;
            if (MODE == 0) {
                qkv_store2(r0,     cc, v00, v01);
                qkv_store2(r0 + 8, cc, v10, v11);
            } else {
                *(float2*)&out[(size_t)r0 * Dd + cc]       = make_float2(v00, v01);
                *(float2*)&out[(size_t)(r0 + 8) * Dd + cc] = make_float2(v10, v11);
            }
        }
    }
}

// ---------------------------------------------------------------------------
// Flash attention on mma.sync (byte-identical to the round-7 PASS).
// ---------------------------------------------------------------------------
#define SQP 36
#define SKP 36
#define VTS 68
#define ATTN_SMEM_BYTES (64000 + 256)
#define LOG2E 1.4426950408889634f

__global__ __launch_bounds__(256)
void attn_mma_kernel(const float* __restrict__ attn_bias) {
    extern __shared__ char smc[];
    unsigned long long* Qp = (unsigned long long*)smc;
    unsigned long long* Kp = (unsigned long long*)(smc + 36864);
    __half* Vt             = (__half*)(smc + 55296);
    float* bias_s          = (float*)(smc + 64000);

    const int tid  = threadIdx.x;
    const int lane = tid & 31;
    const int w    = tid >> 5;
    const int lq   = lane >> 2;
    const int lm   = lane & 3;
    const int bh   = blockIdx.y;
    const int bb   = bh >> 4;
    const int h    = bh & 15;
    const int q0   = blockIdx.x * 128;

    const float* Qg = g_q + ((size_t)bh * Nn + q0) * HD;
    const float* Kg = g_k + (size_t)bh * Nn * HD;
    const float* Vg = g_v + (size_t)bh * Nn * HD;
    const float* bg = attn_bias + (size_t)bb * Nn;

#pragma unroll
    for (int t = 0; t < 4; t++) {
        int task = tid + t * 256;
        int row  = task >> 3;
        int ch   = task & 7;
        const float* src = Qg + (size_t)row * HD + ch * 8;
        float4 v0 = *(const float4*)src;
        float4 v1 = *(const float4*)(src + 4);
        unsigned long long* dst = Qp + row * SQP + ch * 4;
        dst[0] = (unsigned long long)f2tf32(v0.x) | ((unsigned long long)f2tf32(v1.x) << 32);
        dst[1] = (unsigned long long)f2tf32(v0.y) | ((unsigned long long)f2tf32(v1.y) << 32);
        dst[2] = (unsigned long long)f2tf32(v0.z) | ((unsigned long long)f2tf32(v1.z) << 32);
        dst[3] = (unsigned long long)f2tf32(v0.w) | ((unsigned long long)f2tf32(v1.w) << 32);
    }

    float m0r = -1e30f, m1r = -1e30f, l0 = 0.0f, l1 = 0.0f;
    float o[8][4];
#pragma unroll
    for (int nd = 0; nd < 8; nd++)
#pragma unroll
        for (int j = 0; j < 4; j++) o[nd][j] = 0.0f;

    const unsigned long long* Ar0 = Qp + (w * 16 + lq) * SQP;
    const unsigned long long* Ar1 = Ar0 + 8 * SQP;

    for (int kt = 0; kt < Nn / 64; kt++) {
        const int k0 = kt * 64;
        __syncthreads();
#pragma unroll
        for (int t = 0; t < 2; t++) {
            int task = tid + t * 256;
            int key  = task >> 3;
            int ch   = task & 7;
            const float* src = Kg + (size_t)(k0 + key) * HD + ch * 8;
            float4 v0 = *(const float4*)src;
            float4 v1 = *(const float4*)(src + 4);
            unsigned long long* dst = Kp + key * SKP + ch * 4;
            dst[0] = (unsigned long long)f2tf32(v0.x) | ((unsigned long long)f2tf32(v1.x) << 32);
            dst[1] = (unsigned long long)f2tf32(v0.y) | ((unsigned long long)f2tf32(v1.y) << 32);
            dst[2] = (unsigned long long)f2tf32(v0.z) | ((unsigned long long)f2tf32(v1.z) << 32);
            dst[3] = (unsigned long long)f2tf32(v0.w) | ((unsigned long long)f2tf32(v1.w) << 32);
        }
#pragma unroll
        for (int t = 0; t < 2; t++) {
            int task = tid + t * 256;
            int kp   = task >> 4;
            int c4   = task & 15;
            const float* s0 = Vg + (size_t)(k0 + 2 * kp) * HD + c4 * 4;
            float4 a = *(const float4*)s0;
            float4 b = *(const float4*)(s0 + HD);
            *(__half2*)&Vt[(c4 * 4 + 0) * VTS + 2 * kp] = __floats2half2_rn(a.x, b.x);
            *(__half2*)&Vt[(c4 * 4 + 1) * VTS + 2 * kp] = __floats2half2_rn(a.y, b.y);
            *(__half2*)&Vt[(c4 * 4 + 2) * VTS + 2 * kp] = __floats2half2_rn(a.z, b.z);
            *(__half2*)&Vt[(c4 * 4 + 3) * VTS + 2 * kp] = __floats2half2_rn(a.w, b.w);
        }
        if (tid < 64) bias_s[tid] = bg[k0 + tid] * LOG2E;
        __syncthreads();

        float s[8][4];
#pragma unroll
        for (int nb = 0; nb < 8; nb++)
#pragma unroll
            for (int j = 0; j < 4; j++) s[nb][j] = 0.0f;

#pragma unroll
        for (int kk = 0; kk < 8; kk++) {
            uint2 a02 = *(const uint2*)&Ar0[kk * 4 + lm];
            uint2 a13 = *(const uint2*)&Ar1[kk * 4 + lm];
#pragma unroll
            for (int nb = 0; nb < 8; nb++) {
                uint2 b01 = *(const uint2*)&Kp[(nb * 8 + lq) * SKP + kk * 4 + lm];
                mma_tf32(s[nb], a02.x, a13.x, a02.y, a13.y, b01.x, b01.y);
            }
        }

        const float SC = 0.125f * LOG2E;
#pragma unroll
        for (int nb = 0; nb < 8; nb++) {
            float2 bv = *(const float2*)&bias_s[nb * 8 + 2 * lm];
            s[nb][0] = s[nb][0] * SC + bv.x;
            s[nb][1] = s[nb][1] * SC + bv.y;
            s[nb][2] = s[nb][2] * SC + bv.x;
            s[nb][3] = s[nb][3] * SC + bv.y;
        }

        float rm0 = s[0][0], rm1 = s[0][2];
#pragma unroll
        for (int nb = 0; nb < 8; nb++) {
            rm0 = fmaxf(rm0, fmaxf(s[nb][0], s[nb][1]));
            rm1 = fmaxf(rm1, fmaxf(s[nb][2], s[nb][3]));
        }
        rm0 = fmaxf(rm0, __shfl_xor_sync(0xffffffffu, rm0, 1));
        rm0 = fmaxf(rm0, __shfl_xor_sync(0xffffffffu, rm0, 2));
        rm1 = fmaxf(rm1, __shfl_xor_sync(0xffffffffu, rm1, 1));
        rm1 = fmaxf(rm1, __shfl_xor_sync(0xffffffffu, rm1, 2));
        float mn0 = fmaxf(m0r, rm0), mn1 = fmaxf(m1r, rm1);
        float c0 = ex2f(m0r - mn0), c1 = ex2f(m1r - mn1);
        m0r = mn0; m1r = mn1;
        float rs0 = 0.0f, rs1 = 0.0f;
#pragma unroll
        for (int nb = 0; nb < 8; nb++) {
            s[nb][0] = ex2f(s[nb][0] - mn0);
            s[nb][1] = ex2f(s[nb][1] - mn0);
            s[nb][2] = ex2f(s[nb][2] - mn1);
            s[nb][3] = ex2f(s[nb][3] - mn1);
            rs0 += s[nb][0] + s[nb][1];
            rs1 += s[nb][2] + s[nb][3];
        }
        rs0 += __shfl_xor_sync(0xffffffffu, rs0, 1);
        rs0 += __shfl_xor_sync(0xffffffffu, rs0, 2);
        rs1 += __shfl_xor_sync(0xffffffffu, rs1, 1);
        rs1 += __shfl_xor_sync(0xffffffffu, rs1, 2);
        l0 = l0 * c0 + rs0;
        l1 = l1 * c1 + rs1;
#pragma unroll
        for (int nd = 0; nd < 8; nd++) {
            o[nd][0] *= c0; o[nd][1] *= c0;
            o[nd][2] *= c1; o[nd][3] *= c1;
        }

#pragma unroll
        for (int kc = 0; kc < 4; kc++) {
            uint32_t a0 = h2u(__floats2half2_rn(s[2 * kc][0],     s[2 * kc][1]));
            uint32_t a1 = h2u(__floats2half2_rn(s[2 * kc][2],     s[2 * kc][3]));
            uint32_t a2 = h2u(__floats2half2_rn(s[2 * kc + 1][0], s[2 * kc + 1][1]));
            uint32_t a3 = h2u(__floats2half2_rn(s[2 * kc + 1][2], s[2 * kc + 1][3]));
#pragma unroll
            for (int nd = 0; nd < 8; nd++) {
                const __half* vb = &Vt[(nd * 8 + lq) * VTS + kc * 16 + 2 * lm];
                uint32_t b0 = *(const uint32_t*)vb;
                uint32_t b1 = *(const uint32_t*)(vb + 8);
                mma_f16(o[nd], a0, a1, a2, a3, b0, b1);
            }
        }
    }

    float inv0 = 1.0f / l0, inv1 = 1.0f / l1;
    int qr0 = q0 + w * 16 + lq;
    int qr1 = qr0 + 8;
#pragma unroll
    for (int nd = 0; nd < 8; nd++) {
        int col = h * HD + nd * 8 + 2 * lm;
        float2 v0 = make_float2(o[nd][0] * inv0, o[nd][1] * inv0);
        float2 v1 = make_float2(o[nd][2] * inv1, o[nd][3] * inv1);
        *(float2*)&g_attn[((size_t)bb * Nn + qr0) * Dd + col] = v0;
        *(float2*)&g_attn[((size_t)bb * Nn + qr1) * Dd + col] = v1;
    }
}

// ---------------------------------------------------------------------------
// Launch
// ---------------------------------------------------------------------------
extern "C" void kernel_launch(void* const* d_in, const int* in_sizes, int n_in,
                              void* d_out, int out_size) {
    const float* x         = (const float*)d_in[0];
    const float* attn_bias = (const float*)d_in[1];
    const float* w_qkv     = (const float*)d_in[2];
    const float* b_qkv     = (const float*)d_in[3];
    const float* w_proj    = (const float*)d_in[4];
    const float* b_proj    = (const float*)d_in[5];
    float* out             = (float*)d_out;

    cudaFuncSetAttribute(attn_mma_kernel, cudaFuncAttributeMaxDynamicSharedMemorySize,
                         ATTN_SMEM_BYTES);
    cudaFuncSetAttribute(gemm_mma_kernel<QKVC, 0>,
                         cudaFuncAttributeMaxDynamicSharedMemorySize, GEMM_SMEM_BYTES);
    cudaFuncSetAttribute(gemm_mma_kernel<Dd, 1>,
                         cudaFuncAttributeMaxDynamicSharedMemorySize, GEMM_SMEM_BYTES);

    gemm_mma_kernel<QKVC, 0><<<dim3(QKVC / 128, Mm / 128), 256, GEMM_SMEM_BYTES>>>(
        x, w_qkv, b_qkv, nullptr);
    attn_mma_kernel<<<dim3(Nn / 128, Bb * Hh), 256, ATTN_SMEM_BYTES>>>(attn_bias);
    gemm_mma_kernel<Dd, 1><<<dim3(Dd / 128, Mm / 128), 256, GEMM_SMEM_BYTES>>>(
        nullptr, w_proj, b_proj, out);
}

// round 9
// speedup vs baseline: 3.0185x; 1.1973x over previous
#include <cuda_runtime.h>
#include <cuda_fp16.h>
#include <cstdint>

// Problem constants
#define Bb 2
#define Nn 2048
#define Dd 1024
#define Hh 16
#define HD 64
#define Mm (Bb * Nn)          // 4096 tokens
#define QKVC 3072

// ---------------------------------------------------------------------------
// Scratch (device globals; no dynamic allocation allowed)
// ---------------------------------------------------------------------------
__device__ float g_q[Bb * Hh * Nn * HD];
__device__ float g_k[Bb * Hh * Nn * HD];
__device__ float g_v[Bb * Hh * Nn * HD];
__device__ float g_attn[Mm * Dd];

// ---------------------------------------------------------------------------
// Helpers
// ---------------------------------------------------------------------------
__device__ __forceinline__ uint32_t f2tf32(float x) {
    uint32_t r;
    asm("cvt.rna.tf32.f32 %0, %1;" : "=r"(r) : "f"(x));
    return r;
}
__device__ __forceinline__ float ex2f(float x) {
    float r;
    asm("ex2.approx.f32 %0, %1;" : "=f"(r) : "f"(x));
    return r;
}
__device__ __forceinline__ void mma_tf32(float* d, uint32_t a0, uint32_t a1,
                                         uint32_t a2, uint32_t a3,
                                         uint32_t b0, uint32_t b1) {
    asm volatile(
        "mma.sync.aligned.m16n8k8.row.col.f32.tf32.tf32.f32 "
        "{%0,%1,%2,%3}, {%4,%5,%6,%7}, {%8,%9}, {%0,%1,%2,%3};"
        : "+f"(d[0]), "+f"(d[1]), "+f"(d[2]), "+f"(d[3])
        : "r"(a0), "r"(a1), "r"(a2), "r"(a3), "r"(b0), "r"(b1));
}
__device__ __forceinline__ void mma_f16(float* d, uint32_t a0, uint32_t a1,
                                        uint32_t a2, uint32_t a3,
                                        uint32_t b0, uint32_t b1) {
    asm volatile(
        "mma.sync.aligned.m16n8k16.row.col.f32.f16.f16.f32 "
        "{%0,%1,%2,%3}, {%4,%5,%6,%7}, {%8,%9}, {%0,%1,%2,%3};"
        : "+f"(d[0]), "+f"(d[1]), "+f"(d[2]), "+f"(d[3])
        : "r"(a0), "r"(a1), "r"(a2), "r"(a3), "r"(b0), "r"(b1));
}
__device__ __forceinline__ uint32_t h2u(__half2 h) {
    return *(uint32_t*)&h;
}

// ---------------------------------------------------------------------------
// Single-pass TF32 mma.sync GEMM.
// CTA 128x128, 256 thr / 8 warps, warp tile 32x64 (warp grid 4m x 2n), BK=32,
// double-buffered smem. A[M,K], B[K,N] row-major fp32; values rounded to tf32
// at smem-store time. Fragments via scalar LDS (mapping identical to the
// validated attention S-loop).
// smem layout (fp32 words): As [128][34] (stride 34: <=2-way load conflicts),
//                           Bs [32][132] (stride 132, stores staggered).
// MODE 0: qkv epilogue scatter; MODE 1: proj epilogue.
// ---------------------------------------------------------------------------
#define AS_STR 34
#define BS_STR 132
#define A_TILE_W (128 * AS_STR)          // 4352 words
#define B_TILE_W (32 * BS_STR)           // 4224 words
#define GEMM_SMEM_BYTES ((2 * A_TILE_W + 2 * B_TILE_W) * 4)   // 68608

__device__ __forceinline__ void qkv_store2(int m, int c, float v0, float v1) {
    int part = c >> 10;        // 0=q, 1=k, 2=v
    int rem  = c & 1023;
    int h    = rem >> 6;
    int d    = rem & 63;
    int b    = m >> 11;
    int n    = m & 2047;
    float* dst = (part == 0) ? g_q : (part == 1) ? g_k : g_v;
    *(float2*)&dst[(((size_t)b * Hh + h) * Nn + n) * HD + d] = make_float2(v0, v1);
}

__device__ __forceinline__ void storeA_tf32(uint32_t* W, int row, int c4, float4 v) {
    int base = row * AS_STR + c4 * 4;
    uint2 p0 = make_uint2(f2tf32(v.x), f2tf32(v.y));
    uint2 p1 = make_uint2(f2tf32(v.z), f2tf32(v.w));
    *(uint2*)&W[base]     = p0;
    *(uint2*)&W[base + 2] = p1;
}
__device__ __forceinline__ void storeB_tf32(uint32_t* W, int kk, int n4, float4 v) {
    int off0 = ((n4 >> 3) & 1) << 1;         // stagger breaks 4-way STS conflict
    int base = kk * BS_STR + n4 * 4;
    uint2 p0 = make_uint2(f2tf32(v.x), f2tf32(v.y));
    uint2 p1 = make_uint2(f2tf32(v.z), f2tf32(v.w));
    *(uint2*)&W[base + off0]       = p0;
    *(uint2*)&W[base + (2 - off0)] = p1;
}

template <int NDIM, int MODE>
__global__ __launch_bounds__(256)
void gemm_tf32_kernel(const float* __restrict__ Ain,
                      const float* __restrict__ Bw,
                      const float* __restrict__ bias,
                      float* __restrict__ out) {
    extern __shared__ float smf[];
    const float* A = (MODE == 0) ? Ain : g_attn;

    const int tid  = threadIdx.x;
    const int lane = tid & 31;
    const int w    = tid >> 5;
    const int lq   = lane >> 2;
    const int lm   = lane & 3;
    const int wm   = (w & 3) * 32;
    const int wn   = (w >> 2) * 64;
    const int m0   = blockIdx.y * 128;
    const int n0   = blockIdx.x * 128;

    uint32_t* AsW[2] = { (uint32_t*)smf, (uint32_t*)smf + A_TILE_W };
    uint32_t* BsW[2] = { (uint32_t*)smf + 2 * A_TILE_W,
                         (uint32_t*)smf + 2 * A_TILE_W + B_TILE_W };

    float acc[2][8][4];
#pragma unroll
    for (int t = 0; t < 2; t++)
#pragma unroll
        for (int nb = 0; nb < 8; nb++)
#pragma unroll
            for (int e = 0; e < 4; e++) acc[t][nb][e] = 0.0f;

    // B-load column indices with store-stagger compensation (precomputed)
    int cadj[8];
#pragma unroll
    for (int nb = 0; nb < 8; nb++) {
        int ncol = wn + nb * 8 + lq;
        int sw   = ((ncol >> 5) & 1) << 1;
        cadj[nb] = (ncol & ~3) + (((ncol & 3) + sw) & 3);
    }

    // load-task coords
    const int ac4 = tid & 7;     // A: 8 float4 per 32-wide row
    const int bn4 = tid & 31;    // B: 32 float4 per 128-wide row

    float4 av[4], bv[4];
    // prologue: chunk 0
#pragma unroll
    for (int i = 0; i < 4; i++) {
        int fa = tid + i * 256;
        av[i] = *(const float4*)(A  + (size_t)(m0 + (fa >> 3)) * Dd + ac4 * 4);
        bv[i] = *(const float4*)(Bw + (size_t)(fa >> 5) * NDIM + n0 + bn4 * 4);
    }
#pragma unroll
    for (int i = 0; i < 4; i++) {
        int fa = tid + i * 256;
        storeA_tf32(AsW[0], fa >> 3, ac4, av[i]);
        storeB_tf32(BsW[0], fa >> 5, bn4, bv[i]);
    }
    __syncthreads();

    const int NCHUNK = Dd / 32;
    for (int c = 0; c < NCHUNK; c++) {
        const int cur = c & 1;
        const bool has_next = (c + 1 < NCHUNK);
        if (has_next) {
            int k0 = (c + 1) * 32;
#pragma unroll
            for (int i = 0; i < 4; i++) {
                int fa = tid + i * 256;
                av[i] = *(const float4*)(A  + (size_t)(m0 + (fa >> 3)) * Dd + k0 + ac4 * 4);
                bv[i] = *(const float4*)(Bw + (size_t)(k0 + (fa >> 5)) * NDIM + n0 + bn4 * 4);
            }
        }
        const uint32_t* cA = AsW[cur];
        const uint32_t* cB = BsW[cur];

#pragma unroll
        for (int kg = 0; kg < 4; kg++) {
            uint32_t a[2][4];
#pragma unroll
            for (int t = 0; t < 2; t++) {
                int rowA = wm + t * 16 + lq;
                a[t][0] = cA[rowA * AS_STR + kg * 8 + lm];
                a[t][1] = cA[(rowA + 8) * AS_STR + kg * 8 + lm];
                a[t][2] = cA[rowA * AS_STR + kg * 8 + lm + 4];
                a[t][3] = cA[(rowA + 8) * AS_STR + kg * 8 + lm + 4];
            }
#pragma unroll
            for (int nb = 0; nb < 8; nb++) {
                uint32_t b0 = cB[(kg * 8 + lm) * BS_STR + cadj[nb]];
                uint32_t b1 = cB[(kg * 8 + lm + 4) * BS_STR + cadj[nb]];
                mma_tf32(acc[0][nb], a[0][0], a[0][1], a[0][2], a[0][3], b0, b1);
                mma_tf32(acc[1][nb], a[1][0], a[1][1], a[1][2], a[1][3], b0, b1);
            }
        }

        if (has_next) {
            const int nxt = cur ^ 1;
#pragma unroll
            for (int i = 0; i < 4; i++) {
                int fa = tid + i * 256;
                storeA_tf32(AsW[nxt], fa >> 3, ac4, av[i]);
                storeB_tf32(BsW[nxt], fa >> 5, bn4, bv[i]);
            }
            __syncthreads();
        }
    }

    // Epilogue: D rows wm+t*16+lq (+8), cols wn+nb*8+2*lm (+1)
#pragma unroll
    for (int t = 0; t < 2; t++) {
        int r0 = m0 + wm + t * 16 + lq;
#pragma unroll
        for (int nb = 0; nb < 8; nb++) {
            int cc = n0 + wn + nb * 8 + 2 * lm;
            float b0 = bias[cc], b1 = bias[cc + 1];
            float v00 = acc[t][nb][0] + b0, v01 = acc[t][nb][1] + b1;
            float v10 = acc[t][nb][2] + b0, v11 = acc[t][nb][3] + b1;
            if (MODE == 0) {
                qkv_store2(r0,     cc, v00, v01);
                qkv_store2(r0 + 8, cc, v10, v11);
            } else {
                *(float2*)&out[(size_t)r0 * Dd + cc]       = make_float2(v00, v01);
                *(float2*)&out[(size_t)(r0 + 8) * Dd + cc] = make_float2(v10, v11);
            }
        }
    }
}

// ---------------------------------------------------------------------------
// Flash attention on mma.sync (byte-identical to the round-7/8 PASS).
// ---------------------------------------------------------------------------
#define SQP 36
#define SKP 36
#define VTS 68
#define ATTN_SMEM_BYTES (64000 + 256)
#define LOG2E 1.4426950408889634f

__global__ __launch_bounds__(256)
void attn_mma_kernel(const float* __restrict__ attn_bias) {
    extern __shared__ char smc[];
    unsigned long long* Qp = (unsigned long long*)smc;
    unsigned long long* Kp = (unsigned long long*)(smc + 36864);
    __half* Vt             = (__half*)(smc + 55296);
    float* bias_s          = (float*)(smc + 64000);

    const int tid  = threadIdx.x;
    const int lane = tid & 31;
    const int w    = tid >> 5;
    const int lq   = lane >> 2;
    const int lm   = lane & 3;
    const int bh   = blockIdx.y;
    const int bb   = bh >> 4;
    const int h    = bh & 15;
    const int q0   = blockIdx.x * 128;

    const float* Qg = g_q + ((size_t)bh * Nn + q0) * HD;
    const float* Kg = g_k + (size_t)bh * Nn * HD;
    const float* Vg = g_v + (size_t)bh * Nn * HD;
    const float* bg = attn_bias + (size_t)bb * Nn;

#pragma unroll
    for (int t = 0; t < 4; t++) {
        int task = tid + t * 256;
        int row  = task >> 3;
        int ch   = task & 7;
        const float* src = Qg + (size_t)row * HD + ch * 8;
        float4 v0 = *(const float4*)src;
        float4 v1 = *(const float4*)(src + 4);
        unsigned long long* dst = Qp + row * SQP + ch * 4;
        dst[0] = (unsigned long long)f2tf32(v0.x) | ((unsigned long long)f2tf32(v1.x) << 32);
        dst[1] = (unsigned long long)f2tf32(v0.y) | ((unsigned long long)f2tf32(v1.y) << 32);
        dst[2] = (unsigned long long)f2tf32(v0.z) | ((unsigned long long)f2tf32(v1.z) << 32);
        dst[3] = (unsigned long long)f2tf32(v0.w) | ((unsigned long long)f2tf32(v1.w) << 32);
    }

    float m0r = -1e30f, m1r = -1e30f, l0 = 0.0f, l1 = 0.0f;
    float o[8][4];
#pragma unroll
    for (int nd = 0; nd < 8; nd++)
#pragma unroll
        for (int j = 0; j < 4; j++) o[nd][j] = 0.0f;

    const unsigned long long* Ar0 = Qp + (w * 16 + lq) * SQP;
    const unsigned long long* Ar1 = Ar0 + 8 * SQP;

    for (int kt = 0; kt < Nn / 64; kt++) {
        const int k0 = kt * 64;
        __syncthreads();
#pragma unroll
        for (int t = 0; t < 2; t++) {
            int task = tid + t * 256;
            int key  = task >> 3;
            int ch   = task & 7;
            const float* src = Kg + (size_t)(k0 + key) * HD + ch * 8;
            float4 v0 = *(const float4*)src;
            float4 v1 = *(const float4*)(src + 4);
            unsigned long long* dst = Kp + key * SKP + ch * 4;
            dst[0] = (unsigned long long)f2tf32(v0.x) | ((unsigned long long)f2tf32(v1.x) << 32);
            dst[1] = (unsigned long long)f2tf32(v0.y) | ((unsigned long long)f2tf32(v1.y) << 32);
            dst[2] = (unsigned long long)f2tf32(v0.z) | ((unsigned long long)f2tf32(v1.z) << 32);
            dst[3] = (unsigned long long)f2tf32(v0.w) | ((unsigned long long)f2tf32(v1.w) << 32);
        }
#pragma unroll
        for (int t = 0; t < 2; t++) {
            int task = tid + t * 256;
            int kp   = task >> 4;
            int c4   = task & 15;
            const float* s0 = Vg + (size_t)(k0 + 2 * kp) * HD + c4 * 4;
            float4 a = *(const float4*)s0;
            float4 b = *(const float4*)(s0 + HD);
            *(__half2*)&Vt[(c4 * 4 + 0) * VTS + 2 * kp] = __floats2half2_rn(a.x, b.x);
            *(__half2*)&Vt[(c4 * 4 + 1) * VTS + 2 * kp] = __floats2half2_rn(a.y, b.y);
            *(__half2*)&Vt[(c4 * 4 + 2) * VTS + 2 * kp] = __floats2half2_rn(a.z, b.z);
            *(__half2*)&Vt[(c4 * 4 + 3) * VTS + 2 * kp] = __floats2half2_rn(a.w, b.w);
        }
        if (tid < 64) bias_s[tid] = bg[k0 + tid] * LOG2E;
        __syncthreads();

        float s[8][4];
#pragma unroll
        for (int nb = 0; nb < 8; nb++)
#pragma unroll
            for (int j = 0; j < 4; j++) s[nb][j] = 0.0f;

#pragma unroll
        for (int kk = 0; kk < 8; kk++) {
            uint2 a02 = *(const uint2*)&Ar0[kk * 4 + lm];
            uint2 a13 = *(const uint2*)&Ar1[kk * 4 + lm];
#pragma unroll
            for (int nb = 0; nb < 8; nb++) {
                uint2 b01 = *(const uint2*)&Kp[(nb * 8 + lq) * SKP + kk * 4 + lm];
                mma_tf32(s[nb], a02.x, a13.x, a02.y, a13.y, b01.x, b01.y);
            }
        }

        const float SC = 0.125f * LOG2E;
#pragma unroll
        for (int nb = 0; nb < 8; nb++) {
            float2 bv = *(const float2*)&bias_s[nb * 8 + 2 * lm];
            s[nb][0] = s[nb][0] * SC + bv.x;
            s[nb][1] = s[nb][1] * SC + bv.y;
            s[nb][2] = s[nb][2] * SC + bv.x;
            s[nb][3] = s[nb][3] * SC + bv.y;
        }

        float rm0 = s[0][0], rm1 = s[0][2];
#pragma unroll
        for (int nb = 0; nb < 8; nb++) {
            rm0 = fmaxf(rm0, fmaxf(s[nb][0], s[nb][1]));
            rm1 = fmaxf(rm1, fmaxf(s[nb][2], s[nb][3]));
        }
        rm0 = fmaxf(rm0, __shfl_xor_sync(0xffffffffu, rm0, 1));
        rm0 = fmaxf(rm0, __shfl_xor_sync(0xffffffffu, rm0, 2));
        rm1 = fmaxf(rm1, __shfl_xor_sync(0xffffffffu, rm1, 1));
        rm1 = fmaxf(rm1, __shfl_xor_sync(0xffffffffu, rm1, 2));
        float mn0 = fmaxf(m0r, rm0), mn1 = fmaxf(m1r, rm1);
        float c0 = ex2f(m0r - mn0), c1 = ex2f(m1r - mn1);
        m0r = mn0; m1r = mn1;
        float rs0 = 0.0f, rs1 = 0.0f;
#pragma unroll
        for (int nb = 0; nb < 8; nb++) {
            s[nb][0] = ex2f(s[nb][0] - mn0);
            s[nb][1] = ex2f(s[nb][1] - mn0);
            s[nb][2] = ex2f(s[nb][2] - mn1);
            s[nb][3] = ex2f(s[nb][3] - mn1);
            rs0 += s[nb][0] + s[nb][1];
            rs1 += s[nb][2] + s[nb][3];
        }
        rs0 += __shfl_xor_sync(0xffffffffu, rs0, 1);
        rs0 += __shfl_xor_sync(0xffffffffu, rs0, 2);
        rs1 += __shfl_xor_sync(0xffffffffu, rs1, 1);
        rs1 += __shfl_xor_sync(0xffffffffu, rs1, 2);
        l0 = l0 * c0 + rs0;
        l1 = l1 * c1 + rs1;
#pragma unroll
        for (int nd = 0; nd < 8; nd++) {
            o[nd][0] *= c0; o[nd][1] *= c0;
            o[nd][2] *= c1; o[nd][3] *= c1;
        }

#pragma unroll
        for (int kc = 0; kc < 4; kc++) {
            uint32_t a0 = h2u(__floats2half2_rn(s[2 * kc][0],     s[2 * kc][1]));
            uint32_t a1 = h2u(__floats2half2_rn(s[2 * kc][2],     s[2 * kc][3]));
            uint32_t a2 = h2u(__floats2half2_rn(s[2 * kc + 1][0], s[2 * kc + 1][1]));
            uint32_t a3 = h2u(__floats2half2_rn(s[2 * kc + 1][2], s[2 * kc + 1][3]));
#pragma unroll
            for (int nd = 0; nd < 8; nd++) {
                const __half* vb = &Vt[(nd * 8 + lq) * VTS + kc * 16 + 2 * lm];
                uint32_t b0 = *(const uint32_t*)vb;
                uint32_t b1 = *(const uint32_t*)(vb + 8);
                mma_f16(o[nd], a0, a1, a2, a3, b0, b1);
            }
        }
    }

    float inv0 = 1.0f / l0, inv1 = 1.0f / l1;
    int qr0 = q0 + w * 16 + lq;
    int qr1 = qr0 + 8;
#pragma unroll
    for (int nd = 0; nd < 8; nd++) {
        int col = h * HD + nd * 8 + 2 * lm;
        float2 v0 = make_float2(o[nd][0] * inv0, o[nd][1] * inv0);
        float2 v1 = make_float2(o[nd][2] * inv1, o[nd][3] * inv1);
        *(float2*)&g_attn[((size_t)bb * Nn + qr0) * Dd + col] = v0;
        *(float2*)&g_attn[((size_t)bb * Nn + qr1) * Dd + col] = v1;
    }
}

// ---------------------------------------------------------------------------
// Launch
// ---------------------------------------------------------------------------
extern "C" void kernel_launch(void* const* d_in, const int* in_sizes, int n_in,
                              void* d_out, int out_size) {
    const float* x         = (const float*)d_in[0];
    const float* attn_bias = (const float*)d_in[1];
    const float* w_qkv     = (const float*)d_in[2];
    const float* b_qkv     = (const float*)d_in[3];
    const float* w_proj    = (const float*)d_in[4];
    const float* b_proj    = (const float*)d_in[5];
    float* out             = (float*)d_out;

    cudaFuncSetAttribute(attn_mma_kernel, cudaFuncAttributeMaxDynamicSharedMemorySize,
                         ATTN_SMEM_BYTES);
    cudaFuncSetAttribute(gemm_tf32_kernel<QKVC, 0>,
                         cudaFuncAttributeMaxDynamicSharedMemorySize, GEMM_SMEM_BYTES);
    cudaFuncSetAttribute(gemm_tf32_kernel<Dd, 1>,
                         cudaFuncAttributeMaxDynamicSharedMemorySize, GEMM_SMEM_BYTES);

    gemm_tf32_kernel<QKVC, 0><<<dim3(QKVC / 128, Mm / 128), 256, GEMM_SMEM_BYTES>>>(
        x, w_qkv, b_qkv, nullptr);
    attn_mma_kernel<<<dim3(Nn / 128, Bb * Hh), 256, ATTN_SMEM_BYTES>>>(attn_bias);
    gemm_tf32_kernel<Dd, 1><<<dim3(Dd / 128, Mm / 128), 256, GEMM_SMEM_BYTES>>>(
        nullptr, w_proj, b_proj, out);
}

// round 17
// speedup vs baseline: 3.1077x; 1.0295x over previous
#include <cuda_runtime.h>
#include <cuda_fp16.h>
#include <cstdint>

// Problem constants
#define Bb 2
#define Nn 2048
#define Dd 1024
#define Hh 16
#define HD 64
#define Mm (Bb * Nn)          // 4096 tokens
#define QKVC 3072

// ---------------------------------------------------------------------------
// Scratch (device globals; no dynamic allocation allowed)
// ---------------------------------------------------------------------------
__device__ float g_q[Bb * Hh * Nn * HD];
__device__ float g_k[Bb * Hh * Nn * HD];
__device__ float g_v[Bb * Hh * Nn * HD];
__device__ float g_attn[Mm * Dd];

// ---------------------------------------------------------------------------
// Helpers
// ---------------------------------------------------------------------------
__device__ __forceinline__ uint32_t f2tf32(float x) {
    uint32_t r;
    asm("cvt.rna.tf32.f32 %0, %1;" : "=r"(r) : "f"(x));
    return r;
}
__device__ __forceinline__ float ex2f(float x) {
    float r;
    asm("ex2.approx.f32 %0, %1;" : "=f"(r) : "f"(x));
    return r;
}
__device__ __forceinline__ void mma_tf32(float* d, uint32_t a0, uint32_t a1,
                                         uint32_t a2, uint32_t a3,
                                         uint32_t b0, uint32_t b1) {
    asm volatile(
        "mma.sync.aligned.m16n8k8.row.col.f32.tf32.tf32.f32 "
        "{%0,%1,%2,%3}, {%4,%5,%6,%7}, {%8,%9}, {%0,%1,%2,%3};"
        : "+f"(d[0]), "+f"(d[1]), "+f"(d[2]), "+f"(d[3])
        : "r"(a0), "r"(a1), "r"(a2), "r"(a3), "r"(b0), "r"(b1));
}
__device__ __forceinline__ void mma_f16(float* d, uint32_t a0, uint32_t a1,
                                        uint32_t a2, uint32_t a3,
                                        uint32_t b0, uint32_t b1) {
    asm volatile(
        "mma.sync.aligned.m16n8k16.row.col.f32.f16.f16.f32 "
        "{%0,%1,%2,%3}, {%4,%5,%6,%7}, {%8,%9}, {%0,%1,%2,%3};"
        : "+f"(d[0]), "+f"(d[1]), "+f"(d[2]), "+f"(d[3])
        : "r"(a0), "r"(a1), "r"(a2), "r"(a3), "r"(b0), "r"(b1));
}
__device__ __forceinline__ uint32_t h2u(__half2 h) {
    return *(uint32_t*)&h;
}

// ---------------------------------------------------------------------------
// TF32 mma.sync GEMM v3 — interleaved-pair smem (attention-validated scheme).
// CTA 128x128, 512 thr / 16 warps (4m x 4n grid, warp tile 32x32), BK=32,
// double-buffered. smem: u64 elements holding (tf32 k, tf32 k+4) pairs,
// layout [pair p][column], stride 132 (=4 mod 16 -> <=2-way frag loads).
//   A pairs: [p = 4*oct + (k&3)][m 0..127]
//   B pairs: [p][n 0..127]
// Fragments: A = 2 x LDS.64 (a0,a2 / a1,a3), B = 1 x LDS.64 (b0,b1).
// MODE 0: qkv epilogue scatter; MODE 1: proj epilogue.
// ---------------------------------------------------------------------------
#define PSTR 132
#define TILE_U2 (16 * PSTR)                       // u64 elems per tile
#define GEMM_SMEM_BYTES (4 * TILE_U2 * 8)         // 67584

__device__ __forceinline__ void qkv_store2(int m, int c, float v0, float v1) {
    int part = c >> 10;        // 0=q, 1=k, 2=v
    int rem  = c & 1023;
    int h    = rem >> 6;
    int d    = rem & 63;
    int b    = m >> 11;
    int n    = m & 2047;
    float* dst = (part == 0) ? g_q : (part == 1) ? g_k : g_v;
    *(float2*)&dst[(((size_t)b * Hh + h) * Nn + n) * HD + d] = make_float2(v0, v1);
}

template <int NDIM, int MODE>
__global__ __launch_bounds__(512)
void gemm_tf32_v3(const float* __restrict__ Ain,
                  const float* __restrict__ Bw,
                  const float* __restrict__ bias,
                  float* __restrict__ out) {
    extern __shared__ uint2 su[];
    const float* A = (MODE == 0) ? Ain : g_attn;

    const int tid  = threadIdx.x;
    const int lane = tid & 31;
    const int w    = tid >> 5;
    const int lq   = lane >> 2;
    const int lm   = lane & 3;
    const int wm   = (w & 3) * 32;
    const int wn   = (w >> 2) * 32;
    const int m0   = blockIdx.y * 128;
    const int n0   = blockIdx.x * 128;

    uint2* AsB[2] = { su, su + TILE_U2 };
    uint2* BsB[2] = { su + 2 * TILE_U2, su + 3 * TILE_U2 };

    float acc[2][4][4];
#pragma unroll
    for (int t = 0; t < 2; t++)
#pragma unroll
        for (int nb = 0; nb < 4; nb++)
#pragma unroll
            for (int e = 0; e < 4; e++) acc[t][nb][e] = 0.0f;

    // A-load coords: thread covers row am, octave aj (8 consecutive k)
    const int am = tid >> 2;          // 0..127
    const int aj = tid & 3;           // 0..3
    // B-load coords: row pair (8*bj+bm, +4), 4 consecutive n
    const int bj  = tid >> 7;         // 0..3
    const int bm  = (tid >> 5) & 3;   // 0..3
    const int bn4 = tid & 31;         // 0..31

    float4 aLo, aHi, bLo, bHi;

    auto load_chunk = [&](int k0) {
        const float* ap = A + (size_t)(m0 + am) * Dd + k0 + 8 * aj;
        aLo = *(const float4*)ap;
        aHi = *(const float4*)(ap + 4);
        const float* bp = Bw + (size_t)(k0 + 8 * bj + bm) * NDIM + n0 + 4 * bn4;
        bLo = *(const float4*)bp;
        bHi = *(const float4*)(bp + (size_t)4 * NDIM);
    };
    auto store_chunk = [&](int buf) {
        float al[4] = {aLo.x, aLo.y, aLo.z, aLo.w};
        float ah[4] = {aHi.x, aHi.y, aHi.z, aHi.w};
#pragma unroll
        for (int i = 0; i < 4; i++) {
            int e = (i + aj) & 3;          // stagger -> ~2-way store conflicts
            AsB[buf][(4 * aj + e) * PSTR + am] =
                make_uint2(f2tf32(al[e]), f2tf32(ah[e]));
        }
        float bl[4] = {bLo.x, bLo.y, bLo.z, bLo.w};
        float bh[4] = {bHi.x, bHi.y, bHi.z, bHi.w};
        int p = 4 * bj + bm;
#pragma unroll
        for (int i = 0; i < 4; i++) {
            int e = (i + (lane >> 2)) & 3; // stagger by lane>>2: lanes 4 apart
                                           // get distinct banks -> conflict-free
            BsB[buf][p * PSTR + 4 * bn4 + e] =
                make_uint2(f2tf32(bl[e]), f2tf32(bh[e]));
        }
    };

    load_chunk(0);
    store_chunk(0);
    __syncthreads();

    const int NCHUNK = Dd / 32;
    for (int c = 0; c < NCHUNK; c++) {
        const int cur = c & 1;
        const bool has_next = (c + 1 < NCHUNK);
        if (has_next) load_chunk((c + 1) * 32);

        const uint2* cA = AsB[cur];
        const uint2* cB = BsB[cur];
#pragma unroll
        for (int kg = 0; kg < 4; kg++) {
            const int prow = (4 * kg + lm) * PSTR;
            uint2 a02[2], a13[2];
#pragma unroll
            for (int t = 0; t < 2; t++) {
                a02[t] = cA[prow + wm + 16 * t + lq];
                a13[t] = cA[prow + wm + 16 * t + lq + 8];
            }
#pragma unroll
            for (int nb = 0; nb < 4; nb++) {
                uint2 b01 = cB[prow + wn + 8 * nb + lq];
                mma_tf32(acc[0][nb], a02[0].x, a13[0].x, a02[0].y, a13[0].y,
                         b01.x, b01.y);
                mma_tf32(acc[1][nb], a02[1].x, a13[1].x, a02[1].y, a13[1].y,
                         b01.x, b01.y);
            }
        }

        if (has_next) {
            store_chunk(cur ^ 1);
            __syncthreads();
        }
    }

    // Epilogue: rows wm+16t+lq (+8), cols wn+8nb+2lm (+1)
#pragma unroll
    for (int t = 0; t < 2; t++) {
        int r0 = m0 + wm + 16 * t + lq;
#pragma unroll
        for (int nb = 0; nb < 4; nb++) {
            int cc = n0 + wn + nb * 8 + 2 * lm;
            float b0 = bias[cc], b1 = bias[cc + 1];
            float v00 = acc[t][nb][0] + b0, v01 = acc[t][nb][1] + b1;
            float v10 = acc[t][nb][2] + b0, v11 = acc[t][nb][3] + b1;
            if (MODE == 0) {
                qkv_store2(r0,     cc, v00, v01);
                qkv_store2(r0 + 8, cc, v10, v11);
            } else {
                *(float2*)&out[(size_t)r0 * Dd + cc]       = make_float2(v00, v01);
                *(float2*)&out[(size_t)(r0 + 8) * Dd + cc] = make_float2(v10, v11);
            }
        }
    }
}

// ---------------------------------------------------------------------------
// Flash attention on mma.sync (byte-identical to the round-7/8/9 PASS).
// ---------------------------------------------------------------------------
#define SQP 36
#define SKP 36
#define VTS 68
#define ATTN_SMEM_BYTES (64000 + 256)
#define LOG2E 1.4426950408889634f

__global__ __launch_bounds__(256)
void attn_mma_kernel(const float* __restrict__ attn_bias) {
    extern __shared__ char smc[];
    unsigned long long* Qp = (unsigned long long*)smc;
    unsigned long long* Kp = (unsigned long long*)(smc + 36864);
    __half* Vt             = (__half*)(smc + 55296);
    float* bias_s          = (float*)(smc + 64000);

    const int tid  = threadIdx.x;
    const int lane = tid & 31;
    const int w    = tid >> 5;
    const int lq   = lane >> 2;
    const int lm   = lane & 3;
    const int bh   = blockIdx.y;
    const int bb   = bh >> 4;
    const int h    = bh & 15;
    const int q0   = blockIdx.x * 128;

    const float* Qg = g_q + ((size_t)bh * Nn + q0) * HD;
    const float* Kg = g_k + (size_t)bh * Nn * HD;
    const float* Vg = g_v + (size_t)bh * Nn * HD;
    const float* bg = attn_bias + (size_t)bb * Nn;

#pragma unroll
    for (int t = 0; t < 4; t++) {
        int task = tid + t * 256;
        int row  = task >> 3;
        int ch   = task & 7;
        const float* src = Qg + (size_t)row * HD + ch * 8;
        float4 v0 = *(const float4*)src;
        float4 v1 = *(const float4*)(src + 4);
        unsigned long long* dst = Qp + row * SQP + ch * 4;
        dst[0] = (unsigned long long)f2tf32(v0.x) | ((unsigned long long)f2tf32(v1.x) << 32);
        dst[1] = (unsigned long long)f2tf32(v0.y) | ((unsigned long long)f2tf32(v1.y) << 32);
        dst[2] = (unsigned long long)f2tf32(v0.z) | ((unsigned long long)f2tf32(v1.z) << 32);
        dst[3] = (unsigned long long)f2tf32(v0.w) | ((unsigned long long)f2tf32(v1.w) << 32);
    }

    float m0r = -1e30f, m1r = -1e30f, l0 = 0.0f, l1 = 0.0f;
    float o[8][4];
#pragma unroll
    for (int nd = 0; nd < 8; nd++)
#pragma unroll
        for (int j = 0; j < 4; j++) o[nd][j] = 0.0f;

    const unsigned long long* Ar0 = Qp + (w * 16 + lq) * SQP;
    const unsigned long long* Ar1 = Ar0 + 8 * SQP;

    for (int kt = 0; kt < Nn / 64; kt++) {
        const int k0 = kt * 64;
        __syncthreads();
#pragma unroll
        for (int t = 0; t < 2; t++) {
            int task = tid + t * 256;
            int key  = task >> 3;
            int ch   = task & 7;
            const float* src = Kg + (size_t)(k0 + key) * HD + ch * 8;
            float4 v0 = *(const float4*)src;
            float4 v1 = *(const float4*)(src + 4);
            unsigned long long* dst = Kp + key * SKP + ch * 4;
            dst[0] = (unsigned long long)f2tf32(v0.x) | ((unsigned long long)f2tf32(v1.x) << 32);
            dst[1] = (unsigned long long)f2tf32(v0.y) | ((unsigned long long)f2tf32(v1.y) << 32);
            dst[2] = (unsigned long long)f2tf32(v0.z) | ((unsigned long long)f2tf32(v1.z) << 32);
            dst[3] = (unsigned long long)f2tf32(v0.w) | ((unsigned long long)f2tf32(v1.w) << 32);
        }
#pragma unroll
        for (int t = 0; t < 2; t++) {
            int task = tid + t * 256;
            int kp   = task >> 4;
            int c4   = task & 15;
            const float* s0 = Vg + (size_t)(k0 + 2 * kp) * HD + c4 * 4;
            float4 a = *(const float4*)s0;
            float4 b = *(const float4*)(s0 + HD);
            *(__half2*)&Vt[(c4 * 4 + 0) * VTS + 2 * kp] = __floats2half2_rn(a.x, b.x);
            *(__half2*)&Vt[(c4 * 4 + 1) * VTS + 2 * kp] = __floats2half2_rn(a.y, b.y);
            *(__half2*)&Vt[(c4 * 4 + 2) * VTS + 2 * kp] = __floats2half2_rn(a.z, b.z);
            *(__half2*)&Vt[(c4 * 4 + 3) * VTS + 2 * kp] = __floats2half2_rn(a.w, b.w);
        }
        if (tid < 64) bias_s[tid] = bg[k0 + tid] * LOG2E;
        __syncthreads();

        float s[8][4];
#pragma unroll
        for (int nb = 0; nb < 8; nb++)
#pragma unroll
            for (int j = 0; j < 4; j++) s[nb][j] = 0.0f;

#pragma unroll
        for (int kk = 0; kk < 8; kk++) {
            uint2 a02 = *(const uint2*)&Ar0[kk * 4 + lm];
            uint2 a13 = *(const uint2*)&Ar1[kk * 4 + lm];
#pragma unroll
            for (int nb = 0; nb < 8; nb++) {
                uint2 b01 = *(const uint2*)&Kp[(nb * 8 + lq) * SKP + kk * 4 + lm];
                mma_tf32(s[nb], a02.x, a13.x, a02.y, a13.y, b01.x, b01.y);
            }
        }

        const float SC = 0.125f * LOG2E;
#pragma unroll
        for (int nb = 0; nb < 8; nb++) {
            float2 bv = *(const float2*)&bias_s[nb * 8 + 2 * lm];
            s[nb][0] = s[nb][0] * SC + bv.x;
            s[nb][1] = s[nb][1] * SC + bv.y;
            s[nb][2] = s[nb][2] * SC + bv.x;
            s[nb][3] = s[nb][3] * SC + bv.y;
        }

        float rm0 = s[0][0], rm1 = s[0][2];
#pragma unroll
        for (int nb = 0; nb < 8; nb++) {
            rm0 = fmaxf(rm0, fmaxf(s[nb][0], s[nb][1]));
            rm1 = fmaxf(rm1, fmaxf(s[nb][2], s[nb][3]));
        }
        rm0 = fmaxf(rm0, __shfl_xor_sync(0xffffffffu, rm0, 1));
        rm0 = fmaxf(rm0, __shfl_xor_sync(0xffffffffu, rm0, 2));
        rm1 = fmaxf(rm1, __shfl_xor_sync(0xffffffffu, rm1, 1));
        rm1 = fmaxf(rm1, __shfl_xor_sync(0xffffffffu, rm1, 2));
        float mn0 = fmaxf(m0r, rm0), mn1 = fmaxf(m1r, rm1);
        float c0 = ex2f(m0r - mn0), c1 = ex2f(m1r - mn1);
        m0r = mn0; m1r = mn1;
        float rs0 = 0.0f, rs1 = 0.0f;
#pragma unroll
        for (int nb = 0; nb < 8; nb++) {
            s[nb][0] = ex2f(s[nb][0] - mn0);
            s[nb][1] = ex2f(s[nb][1] - mn0);
            s[nb][2] = ex2f(s[nb][2] - mn1);
            s[nb][3] = ex2f(s[nb][3] - mn1);
            rs0 += s[nb][0] + s[nb][1];
            rs1 += s[nb][2] + s[nb][3];
        }
        rs0 += __shfl_xor_sync(0xffffffffu, rs0, 1);
        rs0 += __shfl_xor_sync(0xffffffffu, rs0, 2);
        rs1 += __shfl_xor_sync(0xffffffffu, rs1, 1);
        rs1 += __shfl_xor_sync(0xffffffffu, rs1, 2);
        l0 = l0 * c0 + rs0;
        l1 = l1 * c1 + rs1;
#pragma unroll
        for (int nd = 0; nd < 8; nd++) {
            o[nd][0] *= c0; o[nd][1] *= c0;
            o[nd][2] *= c1; o[nd][3] *= c1;
        }

#pragma unroll
        for (int kc = 0; kc < 4; kc++) {
            uint32_t a0 = h2u(__floats2half2_rn(s[2 * kc][0],     s[2 * kc][1]));
            uint32_t a1 = h2u(__floats2half2_rn(s[2 * kc][2],     s[2 * kc][3]));
            uint32_t a2 = h2u(__floats2half2_rn(s[2 * kc + 1][0], s[2 * kc + 1][1]));
            uint32_t a3 = h2u(__floats2half2_rn(s[2 * kc + 1][2], s[2 * kc + 1][3]));
#pragma unroll
            for (int nd = 0; nd < 8; nd++) {
                const __half* vb = &Vt[(nd * 8 + lq) * VTS + kc * 16 + 2 * lm];
                uint32_t b0 = *(const uint32_t*)vb;
                uint32_t b1 = *(const uint32_t*)(vb + 8);
                mma_f16(o[nd], a0, a1, a2, a3, b0, b1);
            }
        }
    }

    float inv0 = 1.0f / l0, inv1 = 1.0f / l1;
    int qr0 = q0 + w * 16 + lq;
    int qr1 = qr0 + 8;
#pragma unroll
    for (int nd = 0; nd < 8; nd++) {
        int col = h * HD + nd * 8 + 2 * lm;
        float2 v0 = make_float2(o[nd][0] * inv0, o[nd][1] * inv0);
        float2 v1 = make_float2(o[nd][2] * inv1, o[nd][3] * inv1);
        *(float2*)&g_attn[((size_t)bb * Nn + qr0) * Dd + col] = v0;
        *(float2*)&g_attn[((size_t)bb * Nn + qr1) * Dd + col] = v1;
    }
}

// ---------------------------------------------------------------------------
// Launch
// ---------------------------------------------------------------------------
extern "C" void kernel_launch(void* const* d_in, const int* in_sizes, int n_in,
                              void* d_out, int out_size) {
    const float* x         = (const float*)d_in[0];
    const float* attn_bias = (const float*)d_in[1];
    const float* w_qkv     = (const float*)d_in[2];
    const float* b_qkv     = (const float*)d_in[3];
    const float* w_proj    = (const float*)d_in[4];
    const float* b_proj    = (const float*)d_in[5];
    float* out             = (float*)d_out;

    cudaFuncSetAttribute(attn_mma_kernel, cudaFuncAttributeMaxDynamicSharedMemorySize,
                         ATTN_SMEM_BYTES);
    cudaFuncSetAttribute(gemm_tf32_v3<QKVC, 0>,
                         cudaFuncAttributeMaxDynamicSharedMemorySize, GEMM_SMEM_BYTES);
    cudaFuncSetAttribute(gemm_tf32_v3<Dd, 1>,
                         cudaFuncAttributeMaxDynamicSharedMemorySize, GEMM_SMEM_BYTES);

    gemm_tf32_v3<QKVC, 0><<<dim3(QKVC / 128, Mm / 128), 512, GEMM_SMEM_BYTES>>>(
        x, w_qkv, b_qkv, nullptr);
    attn_mma_kernel<<<dim3(Nn / 128, Bb * Hh), 256, ATTN_SMEM_BYTES>>>(attn_bias);
    gemm_tf32_v3<Dd, 1><<<dim3(Dd / 128, Mm / 128), 512, GEMM_SMEM_BYTES>>>(
        nullptr, w_proj, b_proj, out);
}